// round 1
// baseline (speedup 1.0000x reference)
#include <cuda_runtime.h>
#include <cuda_bf16.h>
#include <cstdint>

#define HDIM 128
#define PDIM 18
#define RDIM 18
#define NNODES 50000
#define MAXE 800000
#define NB2 (NNODES * RDIM)          // 900000 buckets (dst*R + r)
#define SCAN_B 1024

// ---------------- scratch (device globals; no allocations allowed) ----------------
__device__ float    g_hidden0[NNODES * HDIM];
__device__ float    g_hidden1[NNODES * HDIM];
__device__ float    g_proba[(size_t)PDIM * MAXE];   // transposed [P][E] for coalescing
__device__ float    g_logits[MAXE];
__device__ float    g_ex[MAXE];
__device__ unsigned g_segmax[NNODES];
__device__ float    g_denom[NNODES];
__device__ float    g_proto_norm[PDIM * HDIM];
__device__ int      g_cnt[NB2];
__device__ int      g_off2[NB2 + 1];
__device__ int      g_bsum[SCAN_B];
__device__ int      g_perm[MAXE];

// ---------------- helpers ----------------
__device__ __forceinline__ unsigned enc_f(float f) {
    unsigned b = __float_as_uint(f);
    return (b & 0x80000000u) ? ~b : (b | 0x80000000u);
}
__device__ __forceinline__ float dec_f(unsigned u) {
    unsigned b = (u & 0x80000000u) ? (u ^ 0x80000000u) : ~u;
    return __uint_as_float(b);
}

// ---------------- misc kernels ----------------
__global__ void k_zero32(int* a, int n) {
    int i = blockIdx.x * blockDim.x + threadIdx.x;
    if (i < n) a[i] = 0;
}

__global__ void k_init_hidden(float* hid, const float* __restrict__ se, int n) {
    int i = blockIdx.x * blockDim.x + threadIdx.x;
    if (i < n) hid[i] = (i < HDIM) ? se[i] : 0.f;
}

__global__ void k_proto_norm(const float* __restrict__ proto, float* __restrict__ pn) {
    int p = threadIdx.y;        // blockDim = (32, PDIM)
    int lane = threadIdx.x;
    float4 v = ((const float4*)(proto + p * HDIM))[lane];
    float ss = v.x * v.x + v.y * v.y + v.z * v.z + v.w * v.w;
    #pragma unroll
    for (int o = 16; o; o >>= 1) ss += __shfl_xor_sync(0xffffffffu, ss, o);
    float inv = 1.f / fmaxf(sqrtf(ss), 1e-12f);
    float4 r = make_float4(v.x * inv, v.y * inv, v.z * inv, v.w * inv);
    ((float4*)(pn + p * HDIM))[lane] = r;
}

// ---------------- sort by (dst*R + r): hist / scan / rank ----------------
__global__ void k_hist(const int* __restrict__ dst, const int* __restrict__ et,
                       int* __restrict__ cnt, int E) {
    int e = blockIdx.x * blockDim.x + threadIdx.x;
    if (e < E) atomicAdd(&cnt[dst[e] * RDIM + et[e]], 1);
}

__global__ void k_scan1(const int* __restrict__ cnt, int* __restrict__ off,
                        int* __restrict__ bsum, int n) {
    __shared__ int s[SCAN_B];
    int t = threadIdx.x;
    int i = blockIdx.x * SCAN_B + t;
    int v = (i < n) ? cnt[i] : 0;
    s[t] = v; __syncthreads();
    #pragma unroll
    for (int d = 1; d < SCAN_B; d <<= 1) {
        int x = (t >= d) ? s[t - d] : 0;
        __syncthreads();
        s[t] += x;
        __syncthreads();
    }
    if (i < n) off[i] = s[t] - v;          // exclusive within block
    if (t == SCAN_B - 1) bsum[blockIdx.x] = s[t];
}

__global__ void k_scan2(int* bsum, int nb) {   // single block, exclusive in place
    __shared__ int s[SCAN_B];
    int t = threadIdx.x;
    int v = (t < nb) ? bsum[t] : 0;
    s[t] = v; __syncthreads();
    #pragma unroll
    for (int d = 1; d < SCAN_B; d <<= 1) {
        int x = (t >= d) ? s[t - d] : 0;
        __syncthreads();
        s[t] += x;
        __syncthreads();
    }
    if (t < nb) bsum[t] = s[t] - v;
}

__global__ void k_scan3(int* off, const int* __restrict__ bsum, int n, int E) {
    int i = blockIdx.x * blockDim.x + threadIdx.x;
    if (i < n) off[i] += bsum[i / SCAN_B];
    if (i == 0) off[n] = E;
}

__global__ void k_rank(const int* __restrict__ dst, const int* __restrict__ et,
                       const int* __restrict__ off, int* __restrict__ run,
                       int* __restrict__ perm, int E) {
    int e = blockIdx.x * blockDim.x + threadIdx.x;
    if (e >= E) return;
    int b = dst[e] * RDIM + et[e];
    int pos = off[b] + atomicAdd(&run[b], 1);
    perm[pos] = e;
}

// ---------------- K1: per-edge logits + proba, atomicMax segment max ----------------
__global__ void __launch_bounds__(128) k_edge_logits(
    const float* __restrict__ hidden,
    const int* __restrict__ src, const int* __restrict__ dst,
    const float* __restrict__ proto_n,
    float* __restrict__ proba, float* __restrict__ logits,
    unsigned* __restrict__ segmax, int E)
{
    __shared__ float ps[PDIM * HDIM];
    for (int i = threadIdx.x; i < PDIM * HDIM; i += blockDim.x) ps[i] = proto_n[i];
    __syncthreads();
    int e = blockIdx.x * blockDim.x + threadIdx.x;
    if (e >= E) return;

    const float4* hp = (const float4*)(hidden + (size_t)src[e] * HDIM);
    float d[PDIM];
    #pragma unroll
    for (int p = 0; p < PDIM; p++) d[p] = 0.f;
    float ss = 0.f;
    #pragma unroll 2
    for (int i = 0; i < HDIM / 4; i++) {
        float4 h = __ldg(hp + i);
        ss += h.x * h.x + h.y * h.y + h.z * h.z + h.w * h.w;
        #pragma unroll
        for (int p = 0; p < PDIM; p++) {
            float4 q = *(const float4*)(ps + p * HDIM + i * 4);
            d[p] += h.x * q.x + h.y * q.y + h.z * q.z + h.w * q.w;
        }
    }
    float inv = 1.f / fmaxf(sqrtf(ss), 1e-12f);
    float mx = -1e30f;
    #pragma unroll
    for (int p = 0; p < PDIM; p++) { d[p] *= inv; mx = fmaxf(mx, d[p]); }
    float sum = 0.f;
    #pragma unroll
    for (int p = 0; p < PDIM; p++) { d[p] = expf(d[p] - mx); sum += d[p]; }
    float rs = 1.f / sum;
    float ent = 0.f;
    #pragma unroll
    for (int p = 0; p < PDIM; p++) {
        float pr = d[p] * rs;
        proba[(size_t)p * E + e] = pr;
        ent -= pr * logf(pr + 1e-8f);
    }
    float lg = -ent;
    logits[e] = lg;
    atomicMax(segmax + dst[e], enc_f(lg));
}

// ---------------- K2: exp(logit - segmax) + denom accumulation ----------------
__global__ void k_edge_exp(const int* __restrict__ dst,
                           const float* __restrict__ logits,
                           const unsigned* __restrict__ segmax,
                           float* __restrict__ ex, float* __restrict__ denom, int E)
{
    int e = blockIdx.x * blockDim.x + threadIdx.x;
    if (e >= E) return;
    int n = dst[e];
    float x = expf(logits[e] - dec_f(segmax[n]));
    ex[e] = x;
    atomicAdd(denom + n, x);
}

// ---------------- K3: warp-per-node segmented aggregation (no atomics) ----------------
__global__ void __launch_bounds__(256) k_node_out(
    const float* __restrict__ multi,   // [R][P][H] slice for this layer
    const int* __restrict__ perm, const int* __restrict__ off2,
    const float* __restrict__ proba, const float* __restrict__ ex,
    const float* __restrict__ denom,
    float* __restrict__ out, int E)
{
    int w = (blockIdx.x * blockDim.x + threadIdx.x) >> 5;
    int lane = threadIdx.x & 31;
    if (w >= NNODES) return;
    const int* ob = off2 + w * RDIM;
    int beg = ob[0];
    int end = __ldg(&off2[w * RDIM + RDIM]);
    float4 acc = make_float4(0.f, 0.f, 0.f, 0.f);
    if (beg != end) {
        float rden = 1.f / denom[w];
        int s = beg;
        for (int r = 0; r < RDIM; r++) {
            int t = __ldg(&ob[r + 1]);
            if (s < t) {
                float cs = 0.f;
                for (int j = s; j < t; j++) {
                    int e = __ldg(&perm[j]);
                    float a = __ldg(&ex[e]) * rden;
                    if (lane < PDIM) cs += a * __ldg(&proba[(size_t)lane * E + e]);
                }
                const float4* M = (const float4*)(multi + (size_t)r * PDIM * HDIM);
                #pragma unroll
                for (int p = 0; p < PDIM; p++) {
                    float c = __shfl_sync(0xffffffffu, cs, p);
                    float4 q = __ldg(M + p * (HDIM / 4) + lane);
                    acc.x += c * q.x; acc.y += c * q.y;
                    acc.z += c * q.z; acc.w += c * q.w;
                }
            }
            s = t;
        }
    }
    *(float4*)(out + (size_t)w * HDIM + lane * 4) = acc;
}

// ---------------- classifier: cosine sims of tails vs normalized protos ----------------
__global__ void __launch_bounds__(128) k_classifier(
    const float* __restrict__ hidden, const int* __restrict__ tails,
    const float* __restrict__ pn, float* __restrict__ out, int B)
{
    __shared__ float ps[PDIM * HDIM];
    for (int i = threadIdx.x; i < PDIM * HDIM; i += blockDim.x) ps[i] = pn[i];
    __syncthreads();
    int t = blockIdx.x * blockDim.x + threadIdx.x;
    if (t >= B) return;
    const float4* hp = (const float4*)(hidden + (size_t)tails[t] * HDIM);
    float d[PDIM];
    #pragma unroll
    for (int p = 0; p < PDIM; p++) d[p] = 0.f;
    float ss = 0.f;
    for (int i = 0; i < HDIM / 4; i++) {
        float4 h = __ldg(hp + i);
        ss += h.x * h.x + h.y * h.y + h.z * h.z + h.w * h.w;
        #pragma unroll
        for (int p = 0; p < PDIM; p++) {
            float4 q = *(const float4*)(ps + p * HDIM + i * 4);
            d[p] += h.x * q.x + h.y * q.y + h.z * q.z + h.w * q.w;
        }
    }
    float inv = 1.f / fmaxf(sqrtf(ss), 1e-12f);
    #pragma unroll
    for (int p = 0; p < PDIM; p++) out[(size_t)t * PDIM + p] = d[p] * inv;
}

// ---------------- host ----------------
static inline int grd(int n, int b) { return (n + b - 1) / b; }

extern "C" void kernel_launch(void* const* d_in, const int* in_sizes, int n_in,
                              void* d_out, int out_size)
{
    const int*   edge_index = (const int*)d_in[0];   // [2, E] int32
    const int*   etype      = (const int*)d_in[1];   // [E]
    const int*   tails      = (const int*)d_in[2];   // [B]
    const float* multi      = (const float*)d_in[3]; // [L, R, P, H]
    const float* proto      = (const float*)d_in[4]; // [L, P, H]
    const float* semb       = (const float*)d_in[5]; // [H]
    float* out = (float*)d_out;

    int E = in_sizes[0] / 2;
    int B = in_sizes[2];
    int L = in_sizes[3] / (RDIM * PDIM * HDIM);
    const int* src = edge_index;
    const int* dst = edge_index + E;

    float *hid0, *hid1, *proba, *logits, *ex, *denom, *pn;
    unsigned* segmax;
    int *cnt, *off2, *bsum, *perm;
    cudaGetSymbolAddress((void**)&hid0,   g_hidden0);
    cudaGetSymbolAddress((void**)&hid1,   g_hidden1);
    cudaGetSymbolAddress((void**)&proba,  g_proba);
    cudaGetSymbolAddress((void**)&logits, g_logits);
    cudaGetSymbolAddress((void**)&ex,     g_ex);
    cudaGetSymbolAddress((void**)&segmax, g_segmax);
    cudaGetSymbolAddress((void**)&denom,  g_denom);
    cudaGetSymbolAddress((void**)&pn,     g_proto_norm);
    cudaGetSymbolAddress((void**)&cnt,    g_cnt);
    cudaGetSymbolAddress((void**)&off2,   g_off2);
    cudaGetSymbolAddress((void**)&bsum,   g_bsum);
    cudaGetSymbolAddress((void**)&perm,   g_perm);

    const int TB = 256;

    // ---- preprocessing: counting sort of edges by (dst*R + r) ----
    k_zero32<<<grd(NB2, TB), TB>>>(cnt, NB2);
    k_hist<<<grd(E, TB), TB>>>(dst, etype, cnt, E);
    int nb = grd(NB2, SCAN_B);
    k_scan1<<<nb, SCAN_B>>>(cnt, off2, bsum, NB2);
    k_scan2<<<1, SCAN_B>>>(bsum, nb);
    k_scan3<<<grd(NB2 + 1, TB), TB>>>(off2, bsum, NB2, E);
    k_zero32<<<grd(NB2, TB), TB>>>(cnt, NB2);
    k_rank<<<grd(E, TB), TB>>>(dst, etype, off2, cnt, perm, E);

    // ---- boundary condition ----
    k_init_hidden<<<grd(NNODES * HDIM, TB), TB>>>(hid0, semb, NNODES * HDIM);

    float* cur = hid0;
    float* nxt = hid1;
    for (int l = 0; l < L; l++) {
        k_zero32<<<grd(NNODES, TB), TB>>>((int*)segmax, NNODES);
        k_zero32<<<grd(NNODES, TB), TB>>>((int*)denom, NNODES);
        k_proto_norm<<<1, dim3(32, PDIM)>>>(proto + (size_t)l * PDIM * HDIM, pn);
        k_edge_logits<<<grd(E, 128), 128>>>(cur, src, dst, pn, proba, logits, segmax, E);
        k_edge_exp<<<grd(E, TB), TB>>>(dst, logits, segmax, ex, denom, E);
        k_node_out<<<grd(NNODES * 32, TB), TB>>>(
            multi + (size_t)l * RDIM * PDIM * HDIM, perm, off2, proba, ex, denom, nxt, E);
        float* tmp = cur; cur = nxt; nxt = tmp;
    }

    k_classifier<<<grd(B, 128), 128>>>(cur, tails, pn, out, B);
}

// round 2
// speedup vs baseline: 1.9112x; 1.9112x over previous
#include <cuda_runtime.h>
#include <cuda_bf16.h>
#include <cstdint>

#define HDIM 128
#define PDIM 18
#define RDIM 18
#define NNODES 50000
#define MAXE 800000
#define NB2 (NNODES * RDIM)          // 900000 buckets (dst*R + r)
#define SCAN_B 1024
#define PSTRIDE 32                   // padded proba row stride (128B aligned)

// ---------------- scratch (device globals; no allocations allowed) ----------------
__device__ float    g_hidden0[NNODES * HDIM];
__device__ float    g_hidden1[NNODES * HDIM];
__device__ float    g_proba[NNODES * PSTRIDE];   // per-NODE proba, padded rows
__device__ float    g_logit[NNODES];             // per-NODE logit (-entropy)
__device__ unsigned g_segmax[NNODES];
__device__ float    g_proto_norm[PDIM * HDIM];
__device__ int      g_cnt[NB2];
__device__ int      g_off2[NB2 + 1];
__device__ int      g_bsum[SCAN_B];
__device__ int      g_perm[MAXE];

// ---------------- helpers ----------------
__device__ __forceinline__ unsigned enc_f(float f) {
    unsigned b = __float_as_uint(f);
    return (b & 0x80000000u) ? ~b : (b | 0x80000000u);
}
__device__ __forceinline__ float dec_f(unsigned u) {
    unsigned b = (u & 0x80000000u) ? (u ^ 0x80000000u) : ~u;
    return __uint_as_float(b);
}

// ---------------- misc kernels ----------------
__global__ void k_zero32(int* a, int n) {
    int i = blockIdx.x * blockDim.x + threadIdx.x;
    if (i < n) a[i] = 0;
}

__global__ void k_init_hidden(float* hid, const float* __restrict__ se, int n) {
    int i = blockIdx.x * blockDim.x + threadIdx.x;
    if (i < n) hid[i] = (i < HDIM) ? se[i] : 0.f;
}

__global__ void k_proto_norm(const float* __restrict__ proto, float* __restrict__ pn) {
    int p = threadIdx.y;        // blockDim = (32, PDIM)
    int lane = threadIdx.x;
    float4 v = ((const float4*)(proto + p * HDIM))[lane];
    float ss = v.x * v.x + v.y * v.y + v.z * v.z + v.w * v.w;
    #pragma unroll
    for (int o = 16; o; o >>= 1) ss += __shfl_xor_sync(0xffffffffu, ss, o);
    float inv = 1.f / fmaxf(sqrtf(ss), 1e-12f);
    float4 r = make_float4(v.x * inv, v.y * inv, v.z * inv, v.w * inv);
    ((float4*)(pn + p * HDIM))[lane] = r;
}

// ---------------- sort by (dst*R + r): hist / scan / rank ----------------
__global__ void k_hist(const int* __restrict__ dst, const int* __restrict__ et,
                       int* __restrict__ cnt, int E) {
    int e = blockIdx.x * blockDim.x + threadIdx.x;
    if (e < E) atomicAdd(&cnt[dst[e] * RDIM + et[e]], 1);
}

__global__ void k_scan1(const int* __restrict__ cnt, int* __restrict__ off,
                        int* __restrict__ bsum, int n) {
    __shared__ int s[SCAN_B];
    int t = threadIdx.x;
    int i = blockIdx.x * SCAN_B + t;
    int v = (i < n) ? cnt[i] : 0;
    s[t] = v; __syncthreads();
    #pragma unroll
    for (int d = 1; d < SCAN_B; d <<= 1) {
        int x = (t >= d) ? s[t - d] : 0;
        __syncthreads();
        s[t] += x;
        __syncthreads();
    }
    if (i < n) off[i] = s[t] - v;          // exclusive within block
    if (t == SCAN_B - 1) bsum[blockIdx.x] = s[t];
}

__global__ void k_scan2(int* bsum, int nb) {   // single block, exclusive in place
    __shared__ int s[SCAN_B];
    int t = threadIdx.x;
    int v = (t < nb) ? bsum[t] : 0;
    s[t] = v; __syncthreads();
    #pragma unroll
    for (int d = 1; d < SCAN_B; d <<= 1) {
        int x = (t >= d) ? s[t - d] : 0;
        __syncthreads();
        s[t] += x;
        __syncthreads();
    }
    if (t < nb) bsum[t] = s[t] - v;
}

__global__ void k_scan3(int* off, const int* __restrict__ bsum, int n, int E) {
    int i = blockIdx.x * blockDim.x + threadIdx.x;
    if (i < n) off[i] += bsum[i / SCAN_B];
    if (i == 0) off[n] = E;
}

__global__ void k_rank(const int* __restrict__ dst, const int* __restrict__ et,
                       const int* __restrict__ off, int* __restrict__ run,
                       int* __restrict__ perm, int E) {
    int e = blockIdx.x * blockDim.x + threadIdx.x;
    if (e >= E) return;
    int b = dst[e] * RDIM + et[e];
    int pos = off[b] + atomicAdd(&run[b], 1);
    perm[pos] = e;
}

// ---------------- K1: PER-NODE logits + proba (16x less work than per-edge) ----------------
__global__ void __launch_bounds__(128) k_node_logits(
    const float* __restrict__ hidden,
    const float* __restrict__ proto_n,
    float* __restrict__ proba, float* __restrict__ logit, int N)
{
    __shared__ float ps[PDIM * HDIM];
    for (int i = threadIdx.x; i < PDIM * HDIM; i += blockDim.x) ps[i] = proto_n[i];
    __syncthreads();
    int n = blockIdx.x * blockDim.x + threadIdx.x;
    if (n >= N) return;

    const float4* hp = (const float4*)(hidden + (size_t)n * HDIM);
    float d[PDIM];
    #pragma unroll
    for (int p = 0; p < PDIM; p++) d[p] = 0.f;
    float ss = 0.f;
    #pragma unroll 2
    for (int i = 0; i < HDIM / 4; i++) {
        float4 h = __ldg(hp + i);
        ss += h.x * h.x + h.y * h.y + h.z * h.z + h.w * h.w;
        #pragma unroll
        for (int p = 0; p < PDIM; p++) {
            float4 q = *(const float4*)(ps + p * HDIM + i * 4);
            d[p] += h.x * q.x + h.y * q.y + h.z * q.z + h.w * q.w;
        }
    }
    float inv = 1.f / fmaxf(sqrtf(ss), 1e-12f);
    float mx = -1e30f;
    #pragma unroll
    for (int p = 0; p < PDIM; p++) { d[p] *= inv; mx = fmaxf(mx, d[p]); }
    float sum = 0.f;
    #pragma unroll
    for (int p = 0; p < PDIM; p++) { d[p] = expf(d[p] - mx); sum += d[p]; }
    float rs = 1.f / sum;
    float ent = 0.f;
    #pragma unroll
    for (int p = 0; p < PDIM; p++) {
        float pr = d[p] * rs;
        proba[(size_t)n * PSTRIDE + p] = pr;
        ent -= pr * logf(pr + 1e-8f);
    }
    logit[n] = -ent;
}

// ---------------- K2: per-edge segment max (atomicMax on encoded float) ----------------
__global__ void k_segmax(const int* __restrict__ src, const int* __restrict__ dst,
                         const float* __restrict__ logit,
                         unsigned* __restrict__ segmax, int E)
{
    int e = blockIdx.x * blockDim.x + threadIdx.x;
    if (e >= E) return;
    atomicMax(segmax + dst[e], enc_f(__ldg(logit + src[e])));
}

// ---------------- K3: warp-per-node aggregation, exp+denom inline, no atomics ----------------
__global__ void __launch_bounds__(256) k_node_out(
    const float* __restrict__ multi,   // [R][P][H] slice for this layer
    const int* __restrict__ perm, const int* __restrict__ off2,
    const int* __restrict__ src,
    const float* __restrict__ logit, const float* __restrict__ proba,
    const unsigned* __restrict__ segmax,
    float* __restrict__ out)
{
    int w = (blockIdx.x * blockDim.x + threadIdx.x) >> 5;
    int lane = threadIdx.x & 31;
    if (w >= NNODES) return;
    const int* ob = off2 + w * RDIM;
    int beg = __ldg(&ob[0]);
    int end = __ldg(&off2[w * RDIM + RDIM]);
    float4 acc = make_float4(0.f, 0.f, 0.f, 0.f);
    if (beg != end) {
        float mx = dec_f(segmax[w]);
        float den = 0.f;
        int s = beg;
        for (int r = 0; r < RDIM; r++) {
            int t = __ldg(&ob[r + 1]);
            if (s < t) {
                float cs = 0.f;
                for (int j = s; j < t; j++) {
                    int e  = __ldg(&perm[j]);
                    int sn = __ldg(&src[e]);
                    float ex = expf(__ldg(&logit[sn]) - mx);   // uniform across warp
                    den += ex;
                    if (lane < PDIM) cs += ex * __ldg(&proba[(size_t)sn * PSTRIDE + lane]);
                }
                const float4* M = (const float4*)(multi + (size_t)r * PDIM * HDIM);
                #pragma unroll
                for (int p = 0; p < PDIM; p++) {
                    float c = __shfl_sync(0xffffffffu, cs, p);
                    float4 q = __ldg(M + p * (HDIM / 4) + lane);
                    acc.x += c * q.x; acc.y += c * q.y;
                    acc.z += c * q.z; acc.w += c * q.w;
                }
            }
            s = t;
        }
        float rden = 1.f / den;
        acc.x *= rden; acc.y *= rden; acc.z *= rden; acc.w *= rden;
    }
    *(float4*)(out + (size_t)w * HDIM + lane * 4) = acc;
}

// ---------------- classifier: cosine sims of tails vs normalized protos ----------------
__global__ void __launch_bounds__(128) k_classifier(
    const float* __restrict__ hidden, const int* __restrict__ tails,
    const float* __restrict__ pn, float* __restrict__ out, int B)
{
    __shared__ float ps[PDIM * HDIM];
    for (int i = threadIdx.x; i < PDIM * HDIM; i += blockDim.x) ps[i] = pn[i];
    __syncthreads();
    int t = blockIdx.x * blockDim.x + threadIdx.x;
    if (t >= B) return;
    const float4* hp = (const float4*)(hidden + (size_t)__ldg(&tails[t]) * HDIM);
    float d[PDIM];
    #pragma unroll
    for (int p = 0; p < PDIM; p++) d[p] = 0.f;
    float ss = 0.f;
    for (int i = 0; i < HDIM / 4; i++) {
        float4 h = __ldg(hp + i);
        ss += h.x * h.x + h.y * h.y + h.z * h.z + h.w * h.w;
        #pragma unroll
        for (int p = 0; p < PDIM; p++) {
            float4 q = *(const float4*)(ps + p * HDIM + i * 4);
            d[p] += h.x * q.x + h.y * q.y + h.z * q.z + h.w * q.w;
        }
    }
    float inv = 1.f / fmaxf(sqrtf(ss), 1e-12f);
    #pragma unroll
    for (int p = 0; p < PDIM; p++) out[(size_t)t * PDIM + p] = d[p] * inv;
}

// ---------------- host ----------------
static inline int grd(int n, int b) { return (n + b - 1) / b; }

extern "C" void kernel_launch(void* const* d_in, const int* in_sizes, int n_in,
                              void* d_out, int out_size)
{
    const int*   edge_index = (const int*)d_in[0];   // [2, E] int32
    const int*   etype      = (const int*)d_in[1];   // [E]
    const int*   tails      = (const int*)d_in[2];   // [B]
    const float* multi      = (const float*)d_in[3]; // [L, R, P, H]
    const float* proto      = (const float*)d_in[4]; // [L, P, H]
    const float* semb       = (const float*)d_in[5]; // [H]
    float* out = (float*)d_out;

    int E = in_sizes[0] / 2;
    int B = in_sizes[2];
    int L = in_sizes[3] / (RDIM * PDIM * HDIM);
    const int* src = edge_index;
    const int* dst = edge_index + E;

    float *hid0, *hid1, *proba, *logit, *pn;
    unsigned* segmax;
    int *cnt, *off2, *bsum, *perm;
    cudaGetSymbolAddress((void**)&hid0,   g_hidden0);
    cudaGetSymbolAddress((void**)&hid1,   g_hidden1);
    cudaGetSymbolAddress((void**)&proba,  g_proba);
    cudaGetSymbolAddress((void**)&logit,  g_logit);
    cudaGetSymbolAddress((void**)&segmax, g_segmax);
    cudaGetSymbolAddress((void**)&pn,     g_proto_norm);
    cudaGetSymbolAddress((void**)&cnt,    g_cnt);
    cudaGetSymbolAddress((void**)&off2,   g_off2);
    cudaGetSymbolAddress((void**)&bsum,   g_bsum);
    cudaGetSymbolAddress((void**)&perm,   g_perm);

    const int TB = 256;

    // ---- preprocessing: counting sort of edges by (dst*R + r) ----
    k_zero32<<<grd(NB2, TB), TB>>>(cnt, NB2);
    k_hist<<<grd(E, TB), TB>>>(dst, etype, cnt, E);
    int nb = grd(NB2, SCAN_B);
    k_scan1<<<nb, SCAN_B>>>(cnt, off2, bsum, NB2);
    k_scan2<<<1, SCAN_B>>>(bsum, nb);
    k_scan3<<<grd(NB2 + 1, TB), TB>>>(off2, bsum, NB2, E);
    k_zero32<<<grd(NB2, TB), TB>>>(cnt, NB2);
    k_rank<<<grd(E, TB), TB>>>(dst, etype, off2, cnt, perm, E);

    // ---- boundary condition ----
    k_init_hidden<<<grd(NNODES * HDIM, TB), TB>>>(hid0, semb, NNODES * HDIM);

    float* cur = hid0;
    float* nxt = hid1;
    for (int l = 0; l < L; l++) {
        k_zero32<<<grd(NNODES, TB), TB>>>((int*)segmax, NNODES);
        k_proto_norm<<<1, dim3(32, PDIM)>>>(proto + (size_t)l * PDIM * HDIM, pn);
        k_node_logits<<<grd(NNODES, 128), 128>>>(cur, pn, proba, logit, NNODES);
        k_segmax<<<grd(E, TB), TB>>>(src, dst, logit, segmax, E);
        k_node_out<<<grd(NNODES * 32, TB), TB>>>(
            multi + (size_t)l * RDIM * PDIM * HDIM, perm, off2,
            src, logit, proba, segmax, nxt);
        float* tmp = cur; cur = nxt; nxt = tmp;
    }

    k_classifier<<<grd(B, 128), 128>>>(cur, tails, pn, out, B);
}

// round 3
// speedup vs baseline: 2.5074x; 1.3120x over previous
#include <cuda_runtime.h>
#include <cuda_bf16.h>
#include <cstdint>

#define HDIM 128
#define PDIM 18
#define RDIM 18
#define NNODES 50000
#define NROWS 50048          // 391 * 128, padded GEMM row count
#define MAXE 800000
#define NB2 (NNODES * RDIM)  // 900000 buckets (dst*R + r)
#define SCAN_B 1024
#define PSTRIDE 32           // padded proba row stride
#define KPAD 352             // 324 padded to 11 chunks of 32
#define KU32 (KPAD / 2)      // 176 u32 per row

// ---------------- scratch (device globals; no allocations allowed) ----------------
__device__ float         g_hidden0[NNODES * HDIM];
__device__ float         g_hidden1[NNODES * HDIM];
__device__ float         g_proba[NNODES * PSTRIDE];
__device__ float         g_exl[NNODES];            // exp(logit) per node
__device__ float         g_rden[NNODES];
__device__ __nv_bfloat16 g_Ahi[(size_t)NROWS * KPAD];
__device__ __nv_bfloat16 g_Alo[(size_t)NROWS * KPAD];
__device__ __nv_bfloat16 g_Bhi[128 * KPAD];
__device__ __nv_bfloat16 g_Blo[128 * KPAD];
__device__ float         g_proto_norm[PDIM * HDIM];
__device__ int           g_cnt[NB2];
__device__ int           g_off2[NB2 + 1];
__device__ int           g_bsum[SCAN_B];
__device__ int           g_perm[MAXE];

// ---------------- misc kernels ----------------
__global__ void k_zero32(int* a, int n) {
    int i = blockIdx.x * blockDim.x + threadIdx.x;
    if (i < n) a[i] = 0;
}

__global__ void k_init_hidden(float* hid, const float* __restrict__ se, int n) {
    int i = blockIdx.x * blockDim.x + threadIdx.x;
    if (i < n) hid[i] = (i < HDIM) ? se[i] : 0.f;
}

__global__ void k_proto_norm(const float* __restrict__ proto, float* __restrict__ pn) {
    int p = threadIdx.y;        // blockDim = (32, PDIM)
    int lane = threadIdx.x;
    float4 v = ((const float4*)(proto + p * HDIM))[lane];
    float ss = v.x * v.x + v.y * v.y + v.z * v.z + v.w * v.w;
    #pragma unroll
    for (int o = 16; o; o >>= 1) ss += __shfl_xor_sync(0xffffffffu, ss, o);
    float inv = 1.f / fmaxf(sqrtf(ss), 1e-12f);
    float4 r = make_float4(v.x * inv, v.y * inv, v.z * inv, v.w * inv);
    ((float4*)(pn + p * HDIM))[lane] = r;
}

// ---------------- sort by (dst*R + r): hist / scan / rank ----------------
__global__ void k_hist(const int* __restrict__ dst, const int* __restrict__ et,
                       int* __restrict__ cnt, int E) {
    int e = blockIdx.x * blockDim.x + threadIdx.x;
    if (e < E) atomicAdd(&cnt[dst[e] * RDIM + et[e]], 1);
}

__global__ void k_scan1(const int* __restrict__ cnt, int* __restrict__ off,
                        int* __restrict__ bsum, int n) {
    __shared__ int s[SCAN_B];
    int t = threadIdx.x;
    int i = blockIdx.x * SCAN_B + t;
    int v = (i < n) ? cnt[i] : 0;
    s[t] = v; __syncthreads();
    #pragma unroll
    for (int d = 1; d < SCAN_B; d <<= 1) {
        int x = (t >= d) ? s[t - d] : 0;
        __syncthreads();
        s[t] += x;
        __syncthreads();
    }
    if (i < n) off[i] = s[t] - v;
    if (t == SCAN_B - 1) bsum[blockIdx.x] = s[t];
}

__global__ void k_scan2(int* bsum, int nb) {
    __shared__ int s[SCAN_B];
    int t = threadIdx.x;
    int v = (t < nb) ? bsum[t] : 0;
    s[t] = v; __syncthreads();
    #pragma unroll
    for (int d = 1; d < SCAN_B; d <<= 1) {
        int x = (t >= d) ? s[t - d] : 0;
        __syncthreads();
        s[t] += x;
        __syncthreads();
    }
    if (t < nb) bsum[t] = s[t] - v;
}

__global__ void k_scan3(int* off, const int* __restrict__ bsum, int n, int E) {
    int i = blockIdx.x * blockDim.x + threadIdx.x;
    if (i < n) off[i] += bsum[i / SCAN_B];
    if (i == 0) off[n] = E;
}

__global__ void k_rank(const int* __restrict__ dst, const int* __restrict__ et,
                       const int* __restrict__ off, int* __restrict__ run,
                       int* __restrict__ perm, int E) {
    int e = blockIdx.x * blockDim.x + threadIdx.x;
    if (e >= E) return;
    int b = dst[e] * RDIM + et[e];
    int pos = off[b] + atomicAdd(&run[b], 1);
    perm[pos] = e;
}

// ---------------- K1: per-node proba + exp(logit) ----------------
__global__ void __launch_bounds__(128) k_node_logits(
    const float* __restrict__ hidden,
    const float* __restrict__ proto_n,
    float* __restrict__ proba, float* __restrict__ exl, int N)
{
    __shared__ float ps[PDIM * HDIM];
    for (int i = threadIdx.x; i < PDIM * HDIM; i += blockDim.x) ps[i] = proto_n[i];
    __syncthreads();
    int n = blockIdx.x * blockDim.x + threadIdx.x;
    if (n >= N) return;

    const float4* hp = (const float4*)(hidden + (size_t)n * HDIM);
    float d[PDIM];
    #pragma unroll
    for (int p = 0; p < PDIM; p++) d[p] = 0.f;
    float ss = 0.f;
    #pragma unroll 2
    for (int i = 0; i < HDIM / 4; i++) {
        float4 h = __ldg(hp + i);
        ss += h.x * h.x + h.y * h.y + h.z * h.z + h.w * h.w;
        #pragma unroll
        for (int p = 0; p < PDIM; p++) {
            float4 q = *(const float4*)(ps + p * HDIM + i * 4);
            d[p] += h.x * q.x + h.y * q.y + h.z * q.z + h.w * q.w;
        }
    }
    float inv = 1.f / fmaxf(sqrtf(ss), 1e-12f);
    float mx = -1e30f;
    #pragma unroll
    for (int p = 0; p < PDIM; p++) { d[p] *= inv; mx = fmaxf(mx, d[p]); }
    float sum = 0.f;
    #pragma unroll
    for (int p = 0; p < PDIM; p++) { d[p] = expf(d[p] - mx); sum += d[p]; }
    float rs = 1.f / sum;
    float ent = 0.f;
    #pragma unroll
    for (int p = 0; p < PDIM; p++) {
        float pr = d[p] * rs;
        proba[(size_t)n * PSTRIDE + p] = pr;
        ent -= pr * logf(pr + 1e-8f);
    }
    // logit = -ent in [-ln18, 0]: exp never overflows, softmax shift-invariant
    exl[n] = expf(-ent);
}

// ---------------- K2: build W coefficients as split-bf16, warp per node ----------------
__global__ void __launch_bounds__(256) k_build_W(
    const int* __restrict__ perm, const int* __restrict__ off2,
    const int* __restrict__ src,
    const float* __restrict__ exl, const float* __restrict__ proba,
    __nv_bfloat16* __restrict__ Ahi, __nv_bfloat16* __restrict__ Alo,
    float* __restrict__ rden)
{
    int w = (blockIdx.x * blockDim.x + threadIdx.x) >> 5;
    int lane = threadIdx.x & 31;
    if (w >= NNODES) return;
    const int* ob = off2 + w * RDIM;
    size_t rowoff = (size_t)w * KPAD;
    int beg = __ldg(&ob[0]);
    int end = __ldg(&off2[w * RDIM + RDIM]);
    const __nv_bfloat16 bz = __float2bfloat16(0.f);

    // zero pad columns 324..351
    if (lane < KPAD - RDIM * PDIM) {
        Ahi[rowoff + RDIM * PDIM + lane] = bz;
        Alo[rowoff + RDIM * PDIM + lane] = bz;
    }
    if (beg == end) {   // isolated node: whole row zero, rden 0
        for (int c = lane; c < RDIM * PDIM; c += 32) {
            Ahi[rowoff + c] = bz;
            Alo[rowoff + c] = bz;
        }
        if (lane == 0) rden[w] = 0.f;
        return;
    }
    float den = 0.f;
    int s = beg;
    for (int r = 0; r < RDIM; r++) {
        int t2 = __ldg(&ob[r + 1]);
        float cs = 0.f;
        for (int j = s; j < t2; j++) {
            int e  = __ldg(&perm[j]);
            int sn = __ldg(&src[e]);
            float ex = __ldg(&exl[sn]);          // uniform across warp
            den += ex;
            if (lane < PDIM) cs += ex * __ldg(&proba[(size_t)sn * PSTRIDE + lane]);
        }
        if (lane < PDIM) {
            __nv_bfloat16 hi = __float2bfloat16(cs);
            Ahi[rowoff + r * PDIM + lane] = hi;
            Alo[rowoff + r * PDIM + lane] =
                __float2bfloat16(cs - __bfloat162float(hi));
        }
        s = t2;
    }
    if (lane == 0) rden[w] = 1.f / den;
}

// ---------------- B^T build: Bt[h][k] = M[k/18][k%18][h], split bf16 ----------------
__global__ void k_build_B(const float* __restrict__ M,
                          __nv_bfloat16* __restrict__ Bhi,
                          __nv_bfloat16* __restrict__ Blo)
{
    int idx = blockIdx.x * blockDim.x + threadIdx.x;
    if (idx >= 128 * KPAD) return;
    int h = idx / KPAD, k = idx % KPAD;
    float v = 0.f;
    if (k < RDIM * PDIM)
        v = __ldg(&M[(size_t)(k / PDIM) * PDIM * HDIM + (k % PDIM) * HDIM + h]);
    __nv_bfloat16 hi = __float2bfloat16(v);
    Bhi[idx] = hi;
    Blo[idx] = __float2bfloat16(v - __bfloat162float(hi));
}

// ---------------- K3: split-bf16 GEMM  C[50048x128] = A[.x352] * Bt^T ----------------
__device__ __forceinline__ void mma_bf16(float* c, const unsigned* a, const unsigned* b) {
    asm volatile(
        "mma.sync.aligned.m16n8k16.row.col.f32.bf16.bf16.f32 "
        "{%0,%1,%2,%3}, {%4,%5,%6,%7}, {%8,%9}, {%0,%1,%2,%3};\n"
        : "+f"(c[0]), "+f"(c[1]), "+f"(c[2]), "+f"(c[3])
        : "r"(a[0]), "r"(a[1]), "r"(a[2]), "r"(a[3]), "r"(b[0]), "r"(b[1]));
}

__global__ void __launch_bounds__(256) k_gemm(
    const __nv_bfloat16* __restrict__ Ahi_, const __nv_bfloat16* __restrict__ Alo_,
    const __nv_bfloat16* __restrict__ Bhi_, const __nv_bfloat16* __restrict__ Blo_,
    const float* __restrict__ rden, float* __restrict__ out)
{
    __shared__ unsigned As[128 * 20];   // stride 20 u32 (40 bf16) -> conflict-free frags
    __shared__ unsigned Bs[128 * 20];
    int tid = threadIdx.x;
    int wid = tid >> 5, lane = tid & 31;
    int wm = wid & 3, wn = wid >> 2;          // warp tile: 32 rows x 64 cols
    int g = lane >> 2, t = lane & 3;
    int rowbase = blockIdx.x * 128;

    float acc[2][8][4];
    #pragma unroll
    for (int mt = 0; mt < 2; mt++)
        #pragma unroll
        for (int nt = 0; nt < 8; nt++)
            #pragma unroll
            for (int c = 0; c < 4; c++) acc[mt][nt][c] = 0.f;

    const unsigned* Ahi = (const unsigned*)Ahi_;
    const unsigned* Alo = (const unsigned*)Alo_;
    const unsigned* Bhi = (const unsigned*)Bhi_;
    const unsigned* Blo = (const unsigned*)Blo_;

    #pragma unroll 1
    for (int pass = 0; pass < 3; pass++) {
        const unsigned* Ag = (pass == 1) ? Alo : Ahi;
        const unsigned* Bg = (pass == 2) ? Blo : Bhi;
        #pragma unroll 1
        for (int kc = 0; kc < 11; kc++) {
            int kb = kc * 16;                 // u32 col offset within row
            __syncthreads();
            #pragma unroll
            for (int i = 0; i < 8; i++) {
                int idx = tid + i * 256;
                int r = idx >> 4, c = idx & 15;
                As[r * 20 + c] = Ag[(size_t)(rowbase + r) * KU32 + kb + c];
                Bs[r * 20 + c] = Bg[(size_t)r * KU32 + kb + c];
            }
            __syncthreads();
            #pragma unroll
            for (int kk = 0; kk < 2; kk++) {
                unsigned b[8][2];
                #pragma unroll
                for (int nt = 0; nt < 8; nt++) {
                    int nr = wn * 64 + nt * 8 + g;
                    b[nt][0] = Bs[nr * 20 + kk * 8 + t];
                    b[nt][1] = Bs[nr * 20 + kk * 8 + t + 4];
                }
                #pragma unroll
                for (int mt = 0; mt < 2; mt++) {
                    int mr = wm * 32 + mt * 16 + g;
                    unsigned a[4];
                    a[0] = As[mr * 20 + kk * 8 + t];
                    a[1] = As[(mr + 8) * 20 + kk * 8 + t];
                    a[2] = As[mr * 20 + kk * 8 + t + 4];
                    a[3] = As[(mr + 8) * 20 + kk * 8 + t + 4];
                    #pragma unroll
                    for (int nt = 0; nt < 8; nt++) mma_bf16(acc[mt][nt], a, b[nt]);
                }
            }
        }
    }

    // epilogue: scale by 1/den, guarded store
    #pragma unroll
    for (int mt = 0; mt < 2; mt++) {
        int r0 = rowbase + wm * 32 + mt * 16 + g;
        int r1 = r0 + 8;
        float s0 = (r0 < NNODES) ? rden[r0] : 0.f;
        float s1 = (r1 < NNODES) ? rden[r1] : 0.f;
        #pragma unroll
        for (int nt = 0; nt < 8; nt++) {
            int col = wn * 64 + nt * 8 + t * 2;
            if (r0 < NNODES) {
                float2 v = make_float2(acc[mt][nt][0] * s0, acc[mt][nt][1] * s0);
                *(float2*)(out + (size_t)r0 * HDIM + col) = v;
            }
            if (r1 < NNODES) {
                float2 v = make_float2(acc[mt][nt][2] * s1, acc[mt][nt][3] * s1);
                *(float2*)(out + (size_t)r1 * HDIM + col) = v;
            }
        }
    }
}

// ---------------- classifier ----------------
__global__ void __launch_bounds__(128) k_classifier(
    const float* __restrict__ hidden, const int* __restrict__ tails,
    const float* __restrict__ pn, float* __restrict__ out, int B)
{
    __shared__ float ps[PDIM * HDIM];
    for (int i = threadIdx.x; i < PDIM * HDIM; i += blockDim.x) ps[i] = pn[i];
    __syncthreads();
    int t = blockIdx.x * blockDim.x + threadIdx.x;
    if (t >= B) return;
    const float4* hp = (const float4*)(hidden + (size_t)__ldg(&tails[t]) * HDIM);
    float d[PDIM];
    #pragma unroll
    for (int p = 0; p < PDIM; p++) d[p] = 0.f;
    float ss = 0.f;
    for (int i = 0; i < HDIM / 4; i++) {
        float4 h = __ldg(hp + i);
        ss += h.x * h.x + h.y * h.y + h.z * h.z + h.w * h.w;
        #pragma unroll
        for (int p = 0; p < PDIM; p++) {
            float4 q = *(const float4*)(ps + p * HDIM + i * 4);
            d[p] += h.x * q.x + h.y * q.y + h.z * q.z + h.w * q.w;
        }
    }
    float inv = 1.f / fmaxf(sqrtf(ss), 1e-12f);
    #pragma unroll
    for (int p = 0; p < PDIM; p++) out[(size_t)t * PDIM + p] = d[p] * inv;
}

// ---------------- host ----------------
static inline int grd(int n, int b) { return (n + b - 1) / b; }

extern "C" void kernel_launch(void* const* d_in, const int* in_sizes, int n_in,
                              void* d_out, int out_size)
{
    const int*   edge_index = (const int*)d_in[0];   // [2, E] int32
    const int*   etype      = (const int*)d_in[1];   // [E]
    const int*   tails      = (const int*)d_in[2];   // [B]
    const float* multi      = (const float*)d_in[3]; // [L, R, P, H]
    const float* proto      = (const float*)d_in[4]; // [L, P, H]
    const float* semb       = (const float*)d_in[5]; // [H]
    float* out = (float*)d_out;

    int E = in_sizes[0] / 2;
    int B = in_sizes[2];
    int L = in_sizes[3] / (RDIM * PDIM * HDIM);
    const int* src = edge_index;
    const int* dst = edge_index + E;

    float *hid0, *hid1, *proba, *exl, *rden, *pn;
    __nv_bfloat16 *Ahi, *Alo, *Bhi, *Blo;
    int *cnt, *off2, *bsum, *perm;
    cudaGetSymbolAddress((void**)&hid0,  g_hidden0);
    cudaGetSymbolAddress((void**)&hid1,  g_hidden1);
    cudaGetSymbolAddress((void**)&proba, g_proba);
    cudaGetSymbolAddress((void**)&exl,   g_exl);
    cudaGetSymbolAddress((void**)&rden,  g_rden);
    cudaGetSymbolAddress((void**)&Ahi,   g_Ahi);
    cudaGetSymbolAddress((void**)&Alo,   g_Alo);
    cudaGetSymbolAddress((void**)&Bhi,   g_Bhi);
    cudaGetSymbolAddress((void**)&Blo,   g_Blo);
    cudaGetSymbolAddress((void**)&pn,    g_proto_norm);
    cudaGetSymbolAddress((void**)&cnt,   g_cnt);
    cudaGetSymbolAddress((void**)&off2,  g_off2);
    cudaGetSymbolAddress((void**)&bsum,  g_bsum);
    cudaGetSymbolAddress((void**)&perm,  g_perm);

    const int TB = 256;

    // ---- preprocessing: counting sort of edges by (dst*R + r) ----
    k_zero32<<<grd(NB2, TB), TB>>>(cnt, NB2);
    k_hist<<<grd(E, TB), TB>>>(dst, etype, cnt, E);
    int nb = grd(NB2, SCAN_B);
    k_scan1<<<nb, SCAN_B>>>(cnt, off2, bsum, NB2);
    k_scan2<<<1, SCAN_B>>>(bsum, nb);
    k_scan3<<<grd(NB2 + 1, TB), TB>>>(off2, bsum, NB2, E);
    k_zero32<<<grd(NB2, TB), TB>>>(cnt, NB2);
    k_rank<<<grd(E, TB), TB>>>(dst, etype, off2, cnt, perm, E);

    // ---- boundary condition ----
    k_init_hidden<<<grd(NNODES * HDIM, TB), TB>>>(hid0, semb, NNODES * HDIM);

    float* cur = hid0;
    float* nxt = hid1;
    for (int l = 0; l < L; l++) {
        k_proto_norm<<<1, dim3(32, PDIM)>>>(proto + (size_t)l * PDIM * HDIM, pn);
        k_node_logits<<<grd(NNODES, 128), 128>>>(cur, pn, proba, exl, NNODES);
        k_build_W<<<grd(NNODES * 32, TB), TB>>>(perm, off2, src, exl, proba,
                                                Ahi, Alo, rden);
        k_build_B<<<grd(128 * KPAD, TB), TB>>>(
            multi + (size_t)l * RDIM * PDIM * HDIM, Bhi, Blo);
        k_gemm<<<NROWS / 128, 256>>>(Ahi, Alo, Bhi, Blo, rden, nxt);
        float* tmp = cur; cur = nxt; nxt = tmp;
    }

    k_classifier<<<grd(B, 128), 128>>>(cur, tails, pn, out, B);
}

// round 4
// speedup vs baseline: 3.3888x; 1.3515x over previous
#include <cuda_runtime.h>
#include <cuda_bf16.h>
#include <cstdint>

#define HDIM 128
#define PDIM 18
#define RDIM 18
#define NNODES 50000
#define NROWS 50048          // 391 * 128, padded GEMM row count
#define MAXE 800000
#define NB2 (NNODES * RDIM)  // 900000 buckets (dst*R + r)
#define SCAN_B 1024
#define PSTRIDE 32           // padded eproba row stride
#define KPAD 352             // 324 padded to 11 chunks of 32
#define KU32 (KPAD / 2)      // 176 u32 per row
#define TS 2560              // smem tile: 128 rows * 20 u32
#define LMAX 3

// ---------------- scratch (device globals; no allocations allowed) ----------------
__device__ float         g_hidden0[NNODES * HDIM];
__device__ float         g_hidden1[NNODES * HDIM];
__device__ float         g_eproba[NNODES * PSTRIDE];  // [n][p]=exl*proba, [n][31]=exl
__device__ float         g_rden[NNODES];
__device__ __nv_bfloat16 g_Ahi[(size_t)NROWS * KPAD];
__device__ __nv_bfloat16 g_Alo[(size_t)NROWS * KPAD];
__device__ __nv_bfloat16 g_Bhi[LMAX * 128 * KPAD];
__device__ __nv_bfloat16 g_Blo[LMAX * 128 * KPAD];
__device__ int           g_cnt[NB2];
__device__ int           g_off2[NB2 + 1];
__device__ int           g_bsum[SCAN_B];
__device__ int           g_srcs[MAXE];                // src node, sorted by (dst,r)

// ---------------- helpers ----------------
__device__ __forceinline__ void cp_async16(void* sdst, const void* gsrc) {
    unsigned s = (unsigned)__cvta_generic_to_shared(sdst);
    asm volatile("cp.async.cg.shared.global [%0], [%1], 16;\n" :: "r"(s), "l"(gsrc));
}
#define CP_COMMIT() asm volatile("cp.async.commit_group;\n" ::: "memory")
#define CP_WAIT(n)  asm volatile("cp.async.wait_group %0;\n" :: "n"(n) : "memory")

__device__ __forceinline__ void mma_bf16(float* c, const unsigned* a, const unsigned* b) {
    asm volatile(
        "mma.sync.aligned.m16n8k16.row.col.f32.bf16.bf16.f32 "
        "{%0,%1,%2,%3}, {%4,%5,%6,%7}, {%8,%9}, {%0,%1,%2,%3};\n"
        : "+f"(c[0]), "+f"(c[1]), "+f"(c[2]), "+f"(c[3])
        : "r"(a[0]), "r"(a[1]), "r"(a[2]), "r"(a[3]), "r"(b[0]), "r"(b[1]));
}

// normalize PDIM proto rows into smem ps[] (called by whole 128-thread block)
__device__ __forceinline__ void proto_to_smem(const float* __restrict__ proto, float* ps) {
    int warp = threadIdx.x >> 5, lane = threadIdx.x & 31;
    for (int p = warp; p < PDIM; p += 4) {
        float4 v = ((const float4*)(proto + p * HDIM))[lane];
        float ss = v.x * v.x + v.y * v.y + v.z * v.z + v.w * v.w;
        #pragma unroll
        for (int o = 16; o; o >>= 1) ss += __shfl_xor_sync(0xffffffffu, ss, o);
        float inv = 1.f / fmaxf(sqrtf(ss), 1e-12f);
        float4 r = make_float4(v.x * inv, v.y * inv, v.z * inv, v.w * inv);
        ((float4*)(ps + p * HDIM))[lane] = r;
    }
    __syncthreads();
}

// ---------------- setup: zero cnt + init hidden ----------------
__global__ void k_setup(int* __restrict__ cnt, float* __restrict__ hid,
                        const float* __restrict__ se) {
    int i = blockIdx.x * blockDim.x + threadIdx.x;
    if (i < NB2) cnt[i] = 0;
    if (i < NNODES * HDIM) hid[i] = (i < HDIM) ? se[i] : 0.f;
}

// ---------------- sort by (dst*R + r): hist / scan / rank ----------------
__global__ void k_hist(const int* __restrict__ dst, const int* __restrict__ et,
                       int* __restrict__ cnt, int E) {
    int e = blockIdx.x * blockDim.x + threadIdx.x;
    if (e < E) atomicAdd(&cnt[dst[e] * RDIM + et[e]], 1);
}

__global__ void k_scan1(const int* __restrict__ cnt, int* __restrict__ off,
                        int* __restrict__ bsum, int n) {
    __shared__ int s[SCAN_B];
    int t = threadIdx.x;
    int i = blockIdx.x * SCAN_B + t;
    int v = (i < n) ? cnt[i] : 0;
    s[t] = v; __syncthreads();
    #pragma unroll
    for (int d = 1; d < SCAN_B; d <<= 1) {
        int x = (t >= d) ? s[t - d] : 0;
        __syncthreads();
        s[t] += x;
        __syncthreads();
    }
    if (i < n) off[i] = s[t] - v;
    if (t == SCAN_B - 1) bsum[blockIdx.x] = s[t];
}

__global__ void k_scan2(int* bsum, int nb) {
    __shared__ int s[SCAN_B];
    int t = threadIdx.x;
    int v = (t < nb) ? bsum[t] : 0;
    s[t] = v; __syncthreads();
    #pragma unroll
    for (int d = 1; d < SCAN_B; d <<= 1) {
        int x = (t >= d) ? s[t - d] : 0;
        __syncthreads();
        s[t] += x;
        __syncthreads();
    }
    if (t < nb) bsum[t] = s[t] - v;
}

__global__ void k_scan3(int* __restrict__ off, const int* __restrict__ bsum,
                        int* __restrict__ cnt, int n, int E) {
    int i = blockIdx.x * blockDim.x + threadIdx.x;
    if (i < n) { off[i] += bsum[i / SCAN_B]; cnt[i] = 0; }
    if (i == 0) off[n] = E;
}

__global__ void k_rank(const int* __restrict__ dst, const int* __restrict__ et,
                       const int* __restrict__ src,
                       const int* __restrict__ off, int* __restrict__ run,
                       int* __restrict__ srcs, int E) {
    int e = blockIdx.x * blockDim.x + threadIdx.x;
    if (e >= E) return;
    int b = dst[e] * RDIM + et[e];
    int pos = off[b] + atomicAdd(&run[b], 1);
    srcs[pos] = src[e];
}

// ---------------- B^T build for ALL layers: Bt[l][h][k] = M[l][k/18][k%18][h] ----------------
__global__ void k_build_B(const float* __restrict__ M,
                          __nv_bfloat16* __restrict__ Bhi,
                          __nv_bfloat16* __restrict__ Blo, int total)
{
    int idx = blockIdx.x * blockDim.x + threadIdx.x;
    if (idx >= total) return;
    int l = idx / (128 * KPAD);
    int rem = idx - l * 128 * KPAD;
    int h = rem / KPAD, k = rem % KPAD;
    float v = 0.f;
    if (k < RDIM * PDIM)
        v = __ldg(&M[(size_t)((l * RDIM + k / PDIM) * PDIM + k % PDIM) * HDIM + h]);
    __nv_bfloat16 hi = __float2bfloat16(v);
    Bhi[idx] = hi;
    Blo[idx] = __float2bfloat16(v - __bfloat162float(hi));
}

// ---------------- K1: per-node eproba (proto-norm inlined) ----------------
__global__ void __launch_bounds__(128) k_node_logits(
    const float* __restrict__ hidden,
    const float* __restrict__ proto,
    float* __restrict__ eproba, int N)
{
    __shared__ float ps[PDIM * HDIM];
    proto_to_smem(proto, ps);
    int n = blockIdx.x * blockDim.x + threadIdx.x;
    if (n >= N) return;

    const float4* hp = (const float4*)(hidden + (size_t)n * HDIM);
    float d[PDIM];
    #pragma unroll
    for (int p = 0; p < PDIM; p++) d[p] = 0.f;
    float ss = 0.f;
    #pragma unroll 2
    for (int i = 0; i < HDIM / 4; i++) {
        float4 h = __ldg(hp + i);
        ss += h.x * h.x + h.y * h.y + h.z * h.z + h.w * h.w;
        #pragma unroll
        for (int p = 0; p < PDIM; p++) {
            float4 q = *(const float4*)(ps + p * HDIM + i * 4);
            d[p] += h.x * q.x + h.y * q.y + h.z * q.z + h.w * q.w;
        }
    }
    float inv = 1.f / fmaxf(sqrtf(ss), 1e-12f);
    float mx = -1e30f;
    #pragma unroll
    for (int p = 0; p < PDIM; p++) { d[p] *= inv; mx = fmaxf(mx, d[p]); }
    float sum = 0.f;
    #pragma unroll
    for (int p = 0; p < PDIM; p++) { d[p] = expf(d[p] - mx); sum += d[p]; }
    float rs = 1.f / sum;
    float ent = 0.f;
    #pragma unroll
    for (int p = 0; p < PDIM; p++) {
        d[p] *= rs;
        ent -= d[p] * logf(d[p] + 1e-8f);
    }
    float exl = expf(-ent);  // logit in [-ln18,0]: shift-free softmax is safe
    #pragma unroll
    for (int p = 0; p < PDIM; p++)
        eproba[(size_t)n * PSTRIDE + p] = d[p] * exl;
    #pragma unroll
    for (int p = PDIM; p < 31; p++) eproba[(size_t)n * PSTRIDE + p] = 0.f;
    eproba[(size_t)n * PSTRIDE + 31] = exl;
}

// ---------------- K2: build W coefficients as split-bf16, warp per node ----------------
__global__ void __launch_bounds__(256) k_build_W(
    const int* __restrict__ srcs, const int* __restrict__ off2,
    const float* __restrict__ eproba,
    __nv_bfloat16* __restrict__ Ahi, __nv_bfloat16* __restrict__ Alo,
    float* __restrict__ rden)
{
    int w = (blockIdx.x * blockDim.x + threadIdx.x) >> 5;
    int lane = threadIdx.x & 31;
    if (w >= NNODES) return;
    size_t rowoff = (size_t)w * KPAD;
    int off = (lane < RDIM + 1) ? __ldg(&off2[w * RDIM + lane]) : 0;
    int beg = __shfl_sync(0xffffffffu, off, 0);
    int end = __shfl_sync(0xffffffffu, off, RDIM);
    const __nv_bfloat16 bz = __float2bfloat16(0.f);

    // zero pad columns 324..351
    if (lane < KPAD - RDIM * PDIM) {
        Ahi[rowoff + RDIM * PDIM + lane] = bz;
        Alo[rowoff + RDIM * PDIM + lane] = bz;
    }
    if (beg == end) {   // isolated node
        for (int c = lane; c < RDIM * PDIM; c += 32) {
            Ahi[rowoff + c] = bz;
            Alo[rowoff + c] = bz;
        }
        if (lane == 31) rden[w] = 0.f;
        return;
    }
    float den = 0.f;     // lane 31 accumulates sum of exl via eproba[..31]
    int s = beg;
    #pragma unroll 1
    for (int r = 0; r < RDIM; r++) {
        int t2 = __shfl_sync(0xffffffffu, off, r + 1);
        float cs = 0.f;
        int j = s;
        for (; j + 1 < t2; j += 2) {
            int sn0 = __ldg(&srcs[j]);
            int sn1 = __ldg(&srcs[j + 1]);
            cs += __ldg(&eproba[(size_t)sn0 * PSTRIDE + lane]);
            cs += __ldg(&eproba[(size_t)sn1 * PSTRIDE + lane]);
        }
        if (j < t2) {
            int sn = __ldg(&srcs[j]);
            cs += __ldg(&eproba[(size_t)sn * PSTRIDE + lane]);
        }
        den += cs;
        if (lane < PDIM) {
            __nv_bfloat16 hi = __float2bfloat16(cs);
            Ahi[rowoff + r * PDIM + lane] = hi;
            Alo[rowoff + r * PDIM + lane] =
                __float2bfloat16(cs - __bfloat162float(hi));
        }
        s = t2;
    }
    if (lane == 31) rden[w] = 1.f / den;
}

// ---------------- K3: fused-pass double-buffered split-bf16 GEMM ----------------
// C[50048x128] = (Ahi+Alo)*Bhi^T + Ahi*Blo^T, epilogue scales by rden.
__global__ void __launch_bounds__(256) k_gemm(
    const __nv_bfloat16* __restrict__ Ahi_, const __nv_bfloat16* __restrict__ Alo_,
    const __nv_bfloat16* __restrict__ Bhi_, const __nv_bfloat16* __restrict__ Blo_,
    const float* __restrict__ rden, float* __restrict__ out)
{
    extern __shared__ unsigned sm[];   // [2 stages][4 tiles][TS]
    int tid = threadIdx.x;
    int wid = tid >> 5, lane = tid & 31;
    int wm = wid & 3, wn = wid >> 2;          // warp tile: 32 rows x 64 cols
    int g = lane >> 2, t = lane & 3;
    int rowbase = blockIdx.x * 128;

    const unsigned* Ag[2] = { (const unsigned*)Ahi_, (const unsigned*)Alo_ };
    const unsigned* Bg[2] = { (const unsigned*)Bhi_, (const unsigned*)Blo_ };

    float acc[2][8][4];
    #pragma unroll
    for (int mt = 0; mt < 2; mt++)
        #pragma unroll
        for (int nt = 0; nt < 8; nt++)
            #pragma unroll
            for (int c = 0; c < 4; c++) acc[mt][nt][c] = 0.f;

    // tile loader: stage in {0,1}, kc chunk index
    auto load_stage = [&](int stage, int kc) {
        unsigned* sb = sm + stage * 4 * TS;
        int kb = kc * 16;
        #pragma unroll
        for (int i = 0; i < 8; i++) {
            const int tile = i >> 1;             // 0:Ahi 1:Alo 2:Bhi 3:Blo
            int q = (i & 1) * 256 + tid;
            int row = q >> 2;
            int c4 = (q & 3) * 4;
            const unsigned* gsrc;
            if (tile < 2) gsrc = Ag[tile] + (size_t)(rowbase + row) * KU32 + kb + c4;
            else          gsrc = Bg[tile - 2] + (size_t)row * KU32 + kb + c4;
            cp_async16(sb + tile * TS + row * 20 + c4, gsrc);
        }
    };

    load_stage(0, 0);
    CP_COMMIT();

    #pragma unroll 1
    for (int kc = 0; kc < 11; kc++) {
        int cur = kc & 1;
        if (kc + 1 < 11) { load_stage(cur ^ 1, kc + 1); CP_COMMIT(); }
        if (kc + 1 < 11) { CP_WAIT(1); } else { CP_WAIT(0); }
        __syncthreads();

        unsigned* s0 = sm + cur * 4 * TS;
        unsigned* As_hi = s0;
        unsigned* As_lo = s0 + TS;
        unsigned* Bs_hi = s0 + 2 * TS;
        unsigned* Bs_lo = s0 + 3 * TS;

        #pragma unroll
        for (int kk = 0; kk < 2; kk++) {
            unsigned ahi[2][4], alo[2][4];
            #pragma unroll
            for (int mt = 0; mt < 2; mt++) {
                int mr = wm * 32 + mt * 16 + g;
                ahi[mt][0] = As_hi[mr * 20 + kk * 8 + t];
                ahi[mt][1] = As_hi[(mr + 8) * 20 + kk * 8 + t];
                ahi[mt][2] = As_hi[mr * 20 + kk * 8 + t + 4];
                ahi[mt][3] = As_hi[(mr + 8) * 20 + kk * 8 + t + 4];
                alo[mt][0] = As_lo[mr * 20 + kk * 8 + t];
                alo[mt][1] = As_lo[(mr + 8) * 20 + kk * 8 + t];
                alo[mt][2] = As_lo[mr * 20 + kk * 8 + t + 4];
                alo[mt][3] = As_lo[(mr + 8) * 20 + kk * 8 + t + 4];
            }
            #pragma unroll
            for (int nt = 0; nt < 8; nt++) {
                int nr = wn * 64 + nt * 8 + g;
                unsigned bhi[2], blo[2];
                bhi[0] = Bs_hi[nr * 20 + kk * 8 + t];
                bhi[1] = Bs_hi[nr * 20 + kk * 8 + t + 4];
                blo[0] = Bs_lo[nr * 20 + kk * 8 + t];
                blo[1] = Bs_lo[nr * 20 + kk * 8 + t + 4];
                #pragma unroll
                for (int mt = 0; mt < 2; mt++) {
                    mma_bf16(acc[mt][nt], ahi[mt], bhi);
                    mma_bf16(acc[mt][nt], alo[mt], bhi);
                    mma_bf16(acc[mt][nt], ahi[mt], blo);
                }
            }
        }
        __syncthreads();
    }

    // epilogue: scale by 1/den, guarded store
    #pragma unroll
    for (int mt = 0; mt < 2; mt++) {
        int r0 = rowbase + wm * 32 + mt * 16 + g;
        int r1 = r0 + 8;
        float s0v = (r0 < NNODES) ? rden[r0] : 0.f;
        float s1v = (r1 < NNODES) ? rden[r1] : 0.f;
        #pragma unroll
        for (int nt = 0; nt < 8; nt++) {
            int col = wn * 64 + nt * 8 + t * 2;
            if (r0 < NNODES) {
                float2 v = make_float2(acc[mt][nt][0] * s0v, acc[mt][nt][1] * s0v);
                *(float2*)(out + (size_t)r0 * HDIM + col) = v;
            }
            if (r1 < NNODES) {
                float2 v = make_float2(acc[mt][nt][2] * s1v, acc[mt][nt][3] * s1v);
                *(float2*)(out + (size_t)r1 * HDIM + col) = v;
            }
        }
    }
}

// ---------------- classifier (proto-norm inlined) ----------------
__global__ void __launch_bounds__(128) k_classifier(
    const float* __restrict__ hidden, const int* __restrict__ tails,
    const float* __restrict__ proto, float* __restrict__ out, int B)
{
    __shared__ float ps[PDIM * HDIM];
    proto_to_smem(proto, ps);
    int t = blockIdx.x * blockDim.x + threadIdx.x;
    if (t >= B) return;
    const float4* hp = (const float4*)(hidden + (size_t)__ldg(&tails[t]) * HDIM);
    float d[PDIM];
    #pragma unroll
    for (int p = 0; p < PDIM; p++) d[p] = 0.f;
    float ss = 0.f;
    for (int i = 0; i < HDIM / 4; i++) {
        float4 h = __ldg(hp + i);
        ss += h.x * h.x + h.y * h.y + h.z * h.z + h.w * h.w;
        #pragma unroll
        for (int p = 0; p < PDIM; p++) {
            float4 q = *(const float4*)(ps + p * HDIM + i * 4);
            d[p] += h.x * q.x + h.y * q.y + h.z * q.z + h.w * q.w;
        }
    }
    float inv = 1.f / fmaxf(sqrtf(ss), 1e-12f);
    #pragma unroll
    for (int p = 0; p < PDIM; p++) out[(size_t)t * PDIM + p] = d[p] * inv;
}

// ---------------- host ----------------
static inline int grd(int n, int b) { return (n + b - 1) / b; }

extern "C" void kernel_launch(void* const* d_in, const int* in_sizes, int n_in,
                              void* d_out, int out_size)
{
    const int*   edge_index = (const int*)d_in[0];   // [2, E] int32
    const int*   etype      = (const int*)d_in[1];   // [E]
    const int*   tails      = (const int*)d_in[2];   // [B]
    const float* multi      = (const float*)d_in[3]; // [L, R, P, H]
    const float* proto      = (const float*)d_in[4]; // [L, P, H]
    const float* semb       = (const float*)d_in[5]; // [H]
    float* out = (float*)d_out;

    int E = in_sizes[0] / 2;
    int B = in_sizes[2];
    int L = in_sizes[3] / (RDIM * PDIM * HDIM);
    const int* src = edge_index;
    const int* dst = edge_index + E;

    float *hid0, *hid1, *eproba, *rden;
    __nv_bfloat16 *Ahi, *Alo, *Bhi, *Blo;
    int *cnt, *off2, *bsum, *srcs;
    cudaGetSymbolAddress((void**)&hid0,   g_hidden0);
    cudaGetSymbolAddress((void**)&hid1,   g_hidden1);
    cudaGetSymbolAddress((void**)&eproba, g_eproba);
    cudaGetSymbolAddress((void**)&rden,   g_rden);
    cudaGetSymbolAddress((void**)&Ahi,    g_Ahi);
    cudaGetSymbolAddress((void**)&Alo,    g_Alo);
    cudaGetSymbolAddress((void**)&Bhi,    g_Bhi);
    cudaGetSymbolAddress((void**)&Blo,    g_Blo);
    cudaGetSymbolAddress((void**)&cnt,    g_cnt);
    cudaGetSymbolAddress((void**)&off2,   g_off2);
    cudaGetSymbolAddress((void**)&bsum,   g_bsum);
    cudaGetSymbolAddress((void**)&srcs,   g_srcs);

    const int TB = 256;
    const int GEMM_SMEM = 2 * 4 * TS * 4;   // 81920 B
    static int smem_set = 0;
    if (!smem_set) {
        cudaFuncSetAttribute(k_gemm, cudaFuncAttributeMaxDynamicSharedMemorySize, GEMM_SMEM);
        smem_set = 1;
    }

    // ---- preprocessing: counting sort of edges by (dst*R + r) ----
    k_setup<<<grd(NNODES * HDIM, TB), TB>>>(cnt, hid0, semb);
    k_hist<<<grd(E, TB), TB>>>(dst, etype, cnt, E);
    int nb = grd(NB2, SCAN_B);
    k_scan1<<<nb, SCAN_B>>>(cnt, off2, bsum, NB2);
    k_scan2<<<1, SCAN_B>>>(bsum, nb);
    k_scan3<<<grd(NB2 + 1, TB), TB>>>(off2, bsum, cnt, NB2, E);
    k_rank<<<grd(E, TB), TB>>>(dst, etype, src, off2, cnt, srcs, E);
    k_build_B<<<grd(L * 128 * KPAD, TB), TB>>>(multi, Bhi, Blo, L * 128 * KPAD);

    float* cur = hid0;
    float* nxt = hid1;
    for (int l = 0; l < L; l++) {
        k_node_logits<<<grd(NNODES, 128), 128>>>(
            cur, proto + (size_t)l * PDIM * HDIM, eproba, NNODES);
        k_build_W<<<grd(NNODES * 32, TB), TB>>>(srcs, off2, eproba, Ahi, Alo, rden);
        k_gemm<<<NROWS / 128, 256, GEMM_SMEM>>>(
            Ahi, Alo,
            Bhi + (size_t)l * 128 * KPAD, Blo + (size_t)l * 128 * KPAD,
            rden, nxt);
        float* tmp = cur; cur = nxt; nxt = tmp;
    }

    k_classifier<<<grd(B, 128), 128>>>(
        cur, tails, proto + (size_t)(L - 1) * PDIM * HDIM, out, B);
}

// round 6
// speedup vs baseline: 4.3043x; 1.2701x over previous
#include <cuda_runtime.h>
#include <cuda_bf16.h>
#include <cstdint>

#define HDIM 128
#define PDIM 18
#define RDIM 18
#define NNODES 50000
#define NTILES 391
#define NROWS (NTILES * 128)     // 50048
#define MAXE 800000
#define SCAN_B 1024
#define PSTRIDE 32
#define KUF 352                  // K padded to 11 chunks of 32 (f32 elems per row)
#define NCH 11
#define SMS 36                   // smem row stride in f32 (32 + 4 pad, 16B-aligned)
#define LMAX 3

// ---------------- scratch (device globals; no allocations allowed) ----------------
__device__ float g_hidden0[NNODES * HDIM];
__device__ float g_hidden1[NNODES * HDIM];
__device__ float g_eproba[NNODES * PSTRIDE];  // [n][p]=exl*proba, [n][31]=exl
__device__ float g_rden[NNODES];
__device__ float g_A[(size_t)NROWS * KUF];    // tf32-rounded W coefficients
__device__ float g_B[LMAX * 128 * KUF];       // tf32-rounded M^T per layer
__device__ int   g_cnt[NNODES];
__device__ int   g_off[NNODES + 1];
__device__ int   g_bsum[SCAN_B];
__device__ int   g_srcs[MAXE];                // packed src | (r<<16), sorted by dst

// ---------------- helpers ----------------
__device__ __forceinline__ float tf32r(float x) {
    uint32_t u;
    asm("cvt.rna.tf32.f32 %0, %1;" : "=r"(u) : "f"(x));
    return __uint_as_float(u);
}

__device__ __forceinline__ void cp_async16(void* sdst, const void* gsrc) {
    unsigned s = (unsigned)__cvta_generic_to_shared(sdst);
    asm volatile("cp.async.cg.shared.global [%0], [%1], 16;\n" :: "r"(s), "l"(gsrc));
}
#define CP_COMMIT() asm volatile("cp.async.commit_group;\n" ::: "memory")
#define CP_WAIT(n)  asm volatile("cp.async.wait_group %0;\n" :: "n"(n) : "memory")

__device__ __forceinline__ void mma_tf32(float* c, const unsigned* a, const unsigned* b) {
    asm volatile(
        "mma.sync.aligned.m16n8k8.row.col.f32.tf32.tf32.f32 "
        "{%0,%1,%2,%3}, {%4,%5,%6,%7}, {%8,%9}, {%0,%1,%2,%3};\n"
        : "+f"(c[0]), "+f"(c[1]), "+f"(c[2]), "+f"(c[3])
        : "r"(a[0]), "r"(a[1]), "r"(a[2]), "r"(a[3]), "r"(b[0]), "r"(b[1]));
}

// normalize PDIM proto rows into smem ps[]
__device__ __forceinline__ void proto_to_smem(const float* __restrict__ proto, float* ps) {
    int warp = threadIdx.x >> 5, lane = threadIdx.x & 31;
    for (int p = warp; p < PDIM; p += 4) {
        float4 v = ((const float4*)(proto + p * HDIM))[lane];
        float ss = v.x * v.x + v.y * v.y + v.z * v.z + v.w * v.w;
        #pragma unroll
        for (int o = 16; o; o >>= 1) ss += __shfl_xor_sync(0xffffffffu, ss, o);
        float inv = 1.f / fmaxf(sqrtf(ss), 1e-12f);
        ((float4*)(ps + p * HDIM))[lane] = make_float4(v.x * inv, v.y * inv, v.z * inv, v.w * inv);
    }
    __syncthreads();
}

// ---------------- setup: zero cnt + init hidden + zero A pad rows ----------------
__global__ void k_setup(int* __restrict__ cnt, float* __restrict__ hid,
                        const float* __restrict__ se, float* __restrict__ A) {
    int i = blockIdx.x * blockDim.x + threadIdx.x;
    if (i < NNODES) cnt[i] = 0;
    if (i < NNODES * HDIM) hid[i] = (i < HDIM) ? se[i] : 0.f;
    if (i < (NROWS - NNODES) * KUF)     // zero GEMM pad rows
        A[(size_t)NNODES * KUF + i] = 0.f;
}

// ---------------- sort by dst: hist / scan / rank ----------------
__global__ void k_hist(const int* __restrict__ dst, int* __restrict__ cnt, int E) {
    int e = blockIdx.x * blockDim.x + threadIdx.x;
    if (e < E) atomicAdd(&cnt[dst[e]], 1);
}

__global__ void k_scan1(const int* __restrict__ cnt, int* __restrict__ off,
                        int* __restrict__ bsum, int n) {
    __shared__ int s[SCAN_B];
    int t = threadIdx.x;
    int i = blockIdx.x * SCAN_B + t;
    int v = (i < n) ? cnt[i] : 0;
    s[t] = v; __syncthreads();
    #pragma unroll
    for (int d = 1; d < SCAN_B; d <<= 1) {
        int x = (t >= d) ? s[t - d] : 0;
        __syncthreads();
        s[t] += x;
        __syncthreads();
    }
    if (i < n) off[i] = s[t] - v;
    if (t == SCAN_B - 1) bsum[blockIdx.x] = s[t];
}

__global__ void k_scan2(int* bsum, int nb) {
    __shared__ int s[SCAN_B];
    int t = threadIdx.x;
    int v = (t < nb) ? bsum[t] : 0;
    s[t] = v; __syncthreads();
    #pragma unroll
    for (int d = 1; d < SCAN_B; d <<= 1) {
        int x = (t >= d) ? s[t - d] : 0;
        __syncthreads();
        s[t] += x;
        __syncthreads();
    }
    if (t < nb) bsum[t] = s[t] - v;
}

__global__ void k_scan3(int* __restrict__ off, const int* __restrict__ bsum,
                        int* __restrict__ cnt, int n, int E) {
    int i = blockIdx.x * blockDim.x + threadIdx.x;
    if (i < n) { off[i] += bsum[i / SCAN_B]; cnt[i] = 0; }
    if (i == 0) off[n] = E;
}

__global__ void k_rank(const int* __restrict__ dst, const int* __restrict__ et,
                       const int* __restrict__ src,
                       const int* __restrict__ off, int* __restrict__ run,
                       int* __restrict__ srcs, int E) {
    int e = blockIdx.x * blockDim.x + threadIdx.x;
    if (e >= E) return;
    int d = dst[e];
    int pos = off[d] + atomicAdd(&run[d], 1);
    srcs[pos] = src[e] | (et[e] << 16);
}

// ---------------- B build (all layers): B[l][h][k] = tf32(M[l][k/18][k%18][h]) ----------------
__global__ void k_build_B(const float* __restrict__ M, float* __restrict__ B, int total)
{
    int idx = blockIdx.x * blockDim.x + threadIdx.x;
    if (idx >= total) return;
    int l = idx / (128 * KUF);
    int rem = idx - l * 128 * KUF;
    int h = rem / KUF, k = rem % KUF;
    float v = 0.f;
    if (k < RDIM * PDIM)
        v = tf32r(__ldg(&M[(size_t)((l * RDIM + k / PDIM) * PDIM + k % PDIM) * HDIM + h]));
    B[idx] = v;
}

// ---------------- K1: per-node eproba ----------------
__global__ void __launch_bounds__(128) k_node_logits(
    const float* __restrict__ hidden, const float* __restrict__ proto,
    float* __restrict__ eproba, int N)
{
    __shared__ float ps[PDIM * HDIM];
    proto_to_smem(proto, ps);
    int n = blockIdx.x * blockDim.x + threadIdx.x;
    if (n >= N) return;

    const float4* hp = (const float4*)(hidden + (size_t)n * HDIM);
    float d[PDIM];
    #pragma unroll
    for (int p = 0; p < PDIM; p++) d[p] = 0.f;
    float ss = 0.f;
    #pragma unroll 2
    for (int i = 0; i < HDIM / 4; i++) {
        float4 h = __ldg(hp + i);
        ss += h.x * h.x + h.y * h.y + h.z * h.z + h.w * h.w;
        #pragma unroll
        for (int p = 0; p < PDIM; p++) {
            float4 q = *(const float4*)(ps + p * HDIM + i * 4);
            d[p] += h.x * q.x + h.y * q.y + h.z * q.z + h.w * q.w;
        }
    }
    float inv = 1.f / fmaxf(sqrtf(ss), 1e-12f);
    float mx = -1e30f;
    #pragma unroll
    for (int p = 0; p < PDIM; p++) { d[p] *= inv; mx = fmaxf(mx, d[p]); }
    float sum = 0.f;
    #pragma unroll
    for (int p = 0; p < PDIM; p++) { d[p] = expf(d[p] - mx); sum += d[p]; }
    float rs = 1.f / sum;
    float ent = 0.f;
    #pragma unroll
    for (int p = 0; p < PDIM; p++) {
        d[p] *= rs;
        ent -= d[p] * logf(d[p] + 1e-8f);
    }
    float exl = expf(-ent);   // logit in [-ln18,0]: shift-free softmax safe
    #pragma unroll
    for (int p = 0; p < PDIM; p++)
        eproba[(size_t)n * PSTRIDE + p] = d[p] * exl;
    #pragma unroll
    for (int p = PDIM; p < 31; p++) eproba[(size_t)n * PSTRIDE + p] = 0.f;
    eproba[(size_t)n * PSTRIDE + 31] = exl;
}

// ---------------- K2: build W (tf32), warp per node, smem accumulation ----------------
__global__ void __launch_bounds__(256) k_build_W(
    const int* __restrict__ srcs, const int* __restrict__ off,
    const float* __restrict__ eproba,
    float* __restrict__ A, float* __restrict__ rden)
{
    __shared__ float sW[8][RDIM * 32];
    int w = (blockIdx.x * blockDim.x + threadIdx.x) >> 5;
    int wl = (threadIdx.x >> 5);
    int lane = threadIdx.x & 31;
    if (w >= NNODES) return;
    float* W = sW[wl];
    size_t rowoff = (size_t)w * KUF;
    int beg = __ldg(&off[w]);
    int end = __ldg(&off[w + 1]);

    // zero slab + pad columns 324..351
    #pragma unroll
    for (int r = 0; r < RDIM; r++) W[r * 32 + lane] = 0.f;
    if (lane < KUF - RDIM * PDIM) A[rowoff + RDIM * PDIM + lane] = 0.f;

    float den = 0.f;   // lane 31 sees sum of exl (eproba[..][31] = exl)
    int j = beg;
    for (; j + 1 < end; j += 2) {
        int p0 = __ldg(&srcs[j]);
        int p1 = __ldg(&srcs[j + 1]);
        float e0 = __ldg(&eproba[(size_t)(p0 & 0xFFFF) * PSTRIDE + lane]);
        float e1 = __ldg(&eproba[(size_t)(p1 & 0xFFFF) * PSTRIDE + lane]);
        den += e0 + e1;
        W[(p0 >> 16) * 32 + lane] += e0;
        W[(p1 >> 16) * 32 + lane] += e1;
    }
    if (j < end) {
        int p0 = __ldg(&srcs[j]);
        float e0 = __ldg(&eproba[(size_t)(p0 & 0xFFFF) * PSTRIDE + lane]);
        den += e0;
        W[(p0 >> 16) * 32 + lane] += e0;
    }

    // writeback: A[w][r*18+p] = tf32(W[r][p]) for p<18
    if (lane < PDIM) {
        #pragma unroll
        for (int r = 0; r < RDIM; r++)
            A[rowoff + r * PDIM + lane] = tf32r(W[r * 32 + lane]);
    }
    if (lane == 31) rden[w] = (beg == end) ? 0.f : (1.f / den);
}

// ---------------- K3: single-pass TF32 GEMM  C[NROWSx128] = A * B^T ----------------
__global__ void __launch_bounds__(256) k_gemm(
    const float* __restrict__ A_, const float* __restrict__ B_,
    const float* __restrict__ rden, float* __restrict__ out)
{
    extern __shared__ unsigned sm[];   // [2 stages][A 128*SMS + B 128*SMS]
    int tid = threadIdx.x;
    int wid = tid >> 5, lane = tid & 31;
    int wm = wid & 3, wn = wid >> 2;   // warp tile: 32 rows x 64 cols
    int g = lane >> 2, t = lane & 3;
    int rowbase = blockIdx.x * 128;

    const unsigned* Ag = (const unsigned*)A_;
    const unsigned* Bg = (const unsigned*)B_;

    float acc[2][8][4];
    #pragma unroll
    for (int mt = 0; mt < 2; mt++)
        #pragma unroll
        for (int nt = 0; nt < 8; nt++)
            #pragma unroll
            for (int c = 0; c < 4; c++) acc[mt][nt][c] = 0.f;

    const int STAGE = 2 * 128 * SMS;   // u32 per stage

    auto load_stage = [&](int stage, int kc) {
        unsigned* sb = sm + stage * STAGE;
        int kb = kc * 32;
        #pragma unroll
        for (int i = 0; i < 4; i++) {
            int q = i * 256 + tid;
            int row = q >> 3;
            int c4 = (q & 7) * 4;
            cp_async16(sb + row * SMS + c4,
                       Ag + (size_t)(rowbase + row) * KUF + kb + c4);
            cp_async16(sb + 128 * SMS + row * SMS + c4,
                       Bg + (size_t)row * KUF + kb + c4);
        }
        CP_COMMIT();
    };

    load_stage(0, 0);

    #pragma unroll 1
    for (int kc = 0; kc < NCH; kc++) {
        int cur = kc & 1;
        if (kc + 1 < NCH) { load_stage(cur ^ 1, kc + 1); CP_WAIT(1); }
        else              { CP_WAIT(0); }
        __syncthreads();

        unsigned* As = sm + cur * STAGE;
        unsigned* Bs = As + 128 * SMS;

        #pragma unroll
        for (int ks = 0; ks < 4; ks++) {
            int kb8 = ks * 8;
            unsigned a[2][4];
            #pragma unroll
            for (int mt = 0; mt < 2; mt++) {
                int mr = wm * 32 + mt * 16 + g;
                a[mt][0] = As[mr * SMS + kb8 + t];
                a[mt][1] = As[(mr + 8) * SMS + kb8 + t];
                a[mt][2] = As[mr * SMS + kb8 + t + 4];
                a[mt][3] = As[(mr + 8) * SMS + kb8 + t + 4];
            }
            #pragma unroll
            for (int nt = 0; nt < 8; nt++) {
                int nr = wn * 64 + nt * 8 + g;
                unsigned b[2];
                b[0] = Bs[nr * SMS + kb8 + t];
                b[1] = Bs[nr * SMS + kb8 + t + 4];
                #pragma unroll
                for (int mt = 0; mt < 2; mt++) mma_tf32(acc[mt][nt], a[mt], b);
            }
        }
        __syncthreads();
    }

    // epilogue: scale by 1/den, guarded store
    #pragma unroll
    for (int mt = 0; mt < 2; mt++) {
        int r0 = rowbase + wm * 32 + mt * 16 + g;
        int r1 = r0 + 8;
        float s0v = (r0 < NNODES) ? __ldg(&rden[r0]) : 0.f;
        float s1v = (r1 < NNODES) ? __ldg(&rden[r1]) : 0.f;
        #pragma unroll
        for (int nt = 0; nt < 8; nt++) {
            int col = wn * 64 + nt * 8 + t * 2;
            if (r0 < NNODES) {
                float2 v = make_float2(acc[mt][nt][0] * s0v, acc[mt][nt][1] * s0v);
                *(float2*)(out + (size_t)r0 * HDIM + col) = v;
            }
            if (r1 < NNODES) {
                float2 v = make_float2(acc[mt][nt][2] * s1v, acc[mt][nt][3] * s1v);
                *(float2*)(out + (size_t)r1 * HDIM + col) = v;
            }
        }
    }
}

// ---------------- classifier ----------------
__global__ void __launch_bounds__(128) k_classifier(
    const float* __restrict__ hidden, const int* __restrict__ tails,
    const float* __restrict__ proto, float* __restrict__ out, int B)
{
    __shared__ float ps[PDIM * HDIM];
    proto_to_smem(proto, ps);
    int t = blockIdx.x * blockDim.x + threadIdx.x;
    if (t >= B) return;
    const float4* hp = (const float4*)(hidden + (size_t)__ldg(&tails[t]) * HDIM);
    float d[PDIM];
    #pragma unroll
    for (int p = 0; p < PDIM; p++) d[p] = 0.f;
    float ss = 0.f;
    for (int i = 0; i < HDIM / 4; i++) {
        float4 h = __ldg(hp + i);
        ss += h.x * h.x + h.y * h.y + h.z * h.z + h.w * h.w;
        #pragma unroll
        for (int p = 0; p < PDIM; p++) {
            float4 q = *(const float4*)(ps + p * HDIM + i * 4);
            d[p] += h.x * q.x + h.y * q.y + h.z * q.z + h.w * q.w;
        }
    }
    float inv = 1.f / fmaxf(sqrtf(ss), 1e-12f);
    #pragma unroll
    for (int p = 0; p < PDIM; p++) out[(size_t)t * PDIM + p] = d[p] * inv;
}

// ---------------- host ----------------
static inline int grd(int n, int b) { return (n + b - 1) / b; }

extern "C" void kernel_launch(void* const* d_in, const int* in_sizes, int n_in,
                              void* d_out, int out_size)
{
    const int*   edge_index = (const int*)d_in[0];
    const int*   etype      = (const int*)d_in[1];
    const int*   tails      = (const int*)d_in[2];
    const float* multi      = (const float*)d_in[3];
    const float* proto      = (const float*)d_in[4];
    const float* semb       = (const float*)d_in[5];
    float* out = (float*)d_out;

    int E = in_sizes[0] / 2;
    int B = in_sizes[2];
    int L = in_sizes[3] / (RDIM * PDIM * HDIM);
    const int* src = edge_index;
    const int* dst = edge_index + E;

    float *hid0, *hid1, *eproba, *rden, *A, *Bm;
    int *cnt, *off, *bsum, *srcs;
    cudaGetSymbolAddress((void**)&hid0,   g_hidden0);
    cudaGetSymbolAddress((void**)&hid1,   g_hidden1);
    cudaGetSymbolAddress((void**)&eproba, g_eproba);
    cudaGetSymbolAddress((void**)&rden,   g_rden);
    cudaGetSymbolAddress((void**)&A,      g_A);
    cudaGetSymbolAddress((void**)&Bm,     g_B);
    cudaGetSymbolAddress((void**)&cnt,    g_cnt);
    cudaGetSymbolAddress((void**)&off,    g_off);
    cudaGetSymbolAddress((void**)&bsum,   g_bsum);
    cudaGetSymbolAddress((void**)&srcs,   g_srcs);

    const int TB = 256;
    const int GEMM_SMEM = 2 * 2 * 128 * SMS * 4;   // 73728 B
    cudaFuncSetAttribute(k_gemm, cudaFuncAttributeMaxDynamicSharedMemorySize, GEMM_SMEM);

    // ---- preprocessing: counting sort of edges by dst ----
    k_setup<<<grd(NNODES * HDIM, TB), TB>>>(cnt, hid0, semb, A);
    k_hist<<<grd(E, TB), TB>>>(dst, cnt, E);
    int nb = grd(NNODES, SCAN_B);
    k_scan1<<<nb, SCAN_B>>>(cnt, off, bsum, NNODES);
    k_scan2<<<1, SCAN_B>>>(bsum, nb);
    k_scan3<<<grd(NNODES + 1, TB), TB>>>(off, bsum, cnt, NNODES, E);
    k_rank<<<grd(E, TB), TB>>>(dst, etype, src, off, cnt, srcs, E);
    k_build_B<<<grd(L * 128 * KUF, TB), TB>>>(multi, Bm, L * 128 * KUF);

    float* cur = hid0;
    float* nxt = hid1;
    for (int l = 0; l < L; l++) {
        k_node_logits<<<grd(NNODES, 128), 128>>>(
            cur, proto + (size_t)l * PDIM * HDIM, eproba, NNODES);
        k_build_W<<<grd(NNODES * 32, TB), TB>>>(srcs, off, eproba, A, rden);
        k_gemm<<<NTILES, 256, GEMM_SMEM>>>(A, Bm + (size_t)l * 128 * KUF, rden, nxt);
        float* tmp = cur; cur = nxt; nxt = tmp;
    }

    k_classifier<<<grd(B, 128), 128>>>(
        cur, tails, proto + (size_t)(L - 1) * PDIM * HDIM, out, B);
}

// round 7
// speedup vs baseline: 4.9919x; 1.1598x over previous
#include <cuda_runtime.h>
#include <cuda_bf16.h>
#include <cstdint>

#define HDIM 128
#define PDIM 18
#define RDIM 18
#define NNODES 50000
#define NTILES 391
#define NROWS (NTILES * 128)     // 50048
#define MAXE 800000
#define SCAN_B 1024
#define PSTRIDE 32
#define KUF 352                  // K padded (bf16 elems per row)
#define KU32 176                 // u32 (bf16x2) per row
#define NCH 11                   // k chunks of 32 bf16 (16 u32)
#define SMS 20                   // smem row stride in u32 (16 + 4 pad)
#define LMAX 3

// ---------------- scratch (device globals; no allocations allowed) ----------------
__device__ float         g_hidden0[NNODES * HDIM];
__device__ float         g_hidden1[NNODES * HDIM];
__device__ float         g_eproba[NNODES * PSTRIDE];  // [n][p]=exl*proba, [n][31]=exl
__device__ float         g_rden[NNODES];
__device__ __nv_bfloat16 g_A[(size_t)NROWS * KUF];    // bf16 W coefficients
__device__ __nv_bfloat16 g_B[LMAX * 128 * KUF];       // bf16 M^T per layer
__device__ int           g_cnt[NNODES];
__device__ int           g_off[NNODES + 1];
__device__ int           g_bsum[SCAN_B];
__device__ int           g_srcs[MAXE];                // packed src | (r<<16), sorted by dst

// ---------------- helpers ----------------
__device__ __forceinline__ void cp_async16(void* sdst, const void* gsrc) {
    unsigned s = (unsigned)__cvta_generic_to_shared(sdst);
    asm volatile("cp.async.cg.shared.global [%0], [%1], 16;\n" :: "r"(s), "l"(gsrc));
}
#define CP_COMMIT() asm volatile("cp.async.commit_group;\n" ::: "memory")
#define CP_WAIT(n)  asm volatile("cp.async.wait_group %0;\n" :: "n"(n) : "memory")

__device__ __forceinline__ void mma_bf16(float* c, const unsigned* a, const unsigned* b) {
    asm volatile(
        "mma.sync.aligned.m16n8k16.row.col.f32.bf16.bf16.f32 "
        "{%0,%1,%2,%3}, {%4,%5,%6,%7}, {%8,%9}, {%0,%1,%2,%3};\n"
        : "+f"(c[0]), "+f"(c[1]), "+f"(c[2]), "+f"(c[3])
        : "r"(a[0]), "r"(a[1]), "r"(a[2]), "r"(a[3]), "r"(b[0]), "r"(b[1]));
}

// normalize PDIM proto rows into smem ps[]
__device__ __forceinline__ void proto_to_smem(const float* __restrict__ proto, float* ps) {
    int warp = threadIdx.x >> 5, lane = threadIdx.x & 31;
    for (int p = warp; p < PDIM; p += 4) {
        float4 v = ((const float4*)(proto + p * HDIM))[lane];
        float ss = v.x * v.x + v.y * v.y + v.z * v.z + v.w * v.w;
        #pragma unroll
        for (int o = 16; o; o >>= 1) ss += __shfl_xor_sync(0xffffffffu, ss, o);
        float inv = 1.f / fmaxf(sqrtf(ss), 1e-12f);
        ((float4*)(ps + p * HDIM))[lane] = make_float4(v.x * inv, v.y * inv, v.z * inv, v.w * inv);
    }
    __syncthreads();
}

// ---------------- setup: zero cnt + init hidden + zero A pad rows + build B ----------------
__global__ void k_setup(int* __restrict__ cnt, float* __restrict__ hid,
                        const float* __restrict__ se,
                        __nv_bfloat16* __restrict__ A,
                        const float* __restrict__ M, __nv_bfloat16* __restrict__ B,
                        int btotal) {
    int i = blockIdx.x * blockDim.x + threadIdx.x;
    if (i < NNODES) cnt[i] = 0;
    if (i < NNODES * HDIM) hid[i] = (i < HDIM) ? se[i] : 0.f;
    if (i < (NROWS - NNODES) * KUF)     // zero GEMM pad rows
        A[(size_t)NNODES * KUF + i] = __float2bfloat16(0.f);
    if (i < btotal) {                   // B[l][h][k] = bf16(M[l][k/18][k%18][h])
        int l = i / (128 * KUF);
        int rem = i - l * 128 * KUF;
        int h = rem / KUF, k = rem % KUF;
        float v = 0.f;
        if (k < RDIM * PDIM)
            v = __ldg(&M[(size_t)((l * RDIM + k / PDIM) * PDIM + k % PDIM) * HDIM + h]);
        B[i] = __float2bfloat16(v);
    }
}

// ---------------- sort by dst: hist / scan / rank ----------------
__global__ void k_hist(const int* __restrict__ dst, int* __restrict__ cnt, int E) {
    int e = blockIdx.x * blockDim.x + threadIdx.x;
    if (e < E) atomicAdd(&cnt[dst[e]], 1);
}

__global__ void k_scan1(const int* __restrict__ cnt, int* __restrict__ off,
                        int* __restrict__ bsum, int n) {
    __shared__ int s[SCAN_B];
    int t = threadIdx.x;
    int i = blockIdx.x * SCAN_B + t;
    int v = (i < n) ? cnt[i] : 0;
    s[t] = v; __syncthreads();
    #pragma unroll
    for (int d = 1; d < SCAN_B; d <<= 1) {
        int x = (t >= d) ? s[t - d] : 0;
        __syncthreads();
        s[t] += x;
        __syncthreads();
    }
    if (i < n) off[i] = s[t] - v;
    if (t == SCAN_B - 1) bsum[blockIdx.x] = s[t];
}

__global__ void k_scan2(int* bsum, int nb) {
    __shared__ int s[SCAN_B];
    int t = threadIdx.x;
    int v = (t < nb) ? bsum[t] : 0;
    s[t] = v; __syncthreads();
    #pragma unroll
    for (int d = 1; d < SCAN_B; d <<= 1) {
        int x = (t >= d) ? s[t - d] : 0;
        __syncthreads();
        s[t] += x;
        __syncthreads();
    }
    if (t < nb) bsum[t] = s[t] - v;
}

__global__ void k_scan3(int* __restrict__ off, const int* __restrict__ bsum,
                        int* __restrict__ cnt, int n, int E) {
    int i = blockIdx.x * blockDim.x + threadIdx.x;
    if (i < n) { off[i] += bsum[i / SCAN_B]; cnt[i] = 0; }
    if (i == 0) off[n] = E;
}

__global__ void k_rank(const int* __restrict__ dst, const int* __restrict__ et,
                       const int* __restrict__ src,
                       const int* __restrict__ off, int* __restrict__ run,
                       int* __restrict__ srcs, int E) {
    int e = blockIdx.x * blockDim.x + threadIdx.x;
    if (e >= E) return;
    int d = dst[e];
    int pos = off[d] + atomicAdd(&run[d], 1);
    srcs[pos] = src[e] | (et[e] << 16);
}

// ---------------- K1: per-node eproba ----------------
__global__ void __launch_bounds__(128) k_node_logits(
    const float* __restrict__ hidden, const float* __restrict__ proto,
    float* __restrict__ eproba, int N)
{
    __shared__ float ps[PDIM * HDIM];
    proto_to_smem(proto, ps);
    int n = blockIdx.x * blockDim.x + threadIdx.x;
    if (n >= N) return;

    const float4* hp = (const float4*)(hidden + (size_t)n * HDIM);
    float d[PDIM];
    #pragma unroll
    for (int p = 0; p < PDIM; p++) d[p] = 0.f;
    float ss = 0.f;
    #pragma unroll 2
    for (int i = 0; i < HDIM / 4; i++) {
        float4 h = __ldg(hp + i);
        ss += h.x * h.x + h.y * h.y + h.z * h.z + h.w * h.w;
        #pragma unroll
        for (int p = 0; p < PDIM; p++) {
            float4 q = *(const float4*)(ps + p * HDIM + i * 4);
            d[p] += h.x * q.x + h.y * q.y + h.z * q.z + h.w * q.w;
        }
    }
    float inv = 1.f / fmaxf(sqrtf(ss), 1e-12f);
    float mx = -1e30f;
    #pragma unroll
    for (int p = 0; p < PDIM; p++) { d[p] *= inv; mx = fmaxf(mx, d[p]); }
    float sum = 0.f;
    #pragma unroll
    for (int p = 0; p < PDIM; p++) { d[p] = expf(d[p] - mx); sum += d[p]; }
    float rs = 1.f / sum;
    float ent = 0.f;
    #pragma unroll
    for (int p = 0; p < PDIM; p++) {
        d[p] *= rs;
        ent -= d[p] * logf(d[p] + 1e-8f);
    }
    float exl = expf(-ent);   // logit in [-ln18,0]: shift-free softmax safe
    #pragma unroll
    for (int p = 0; p < PDIM; p++)
        eproba[(size_t)n * PSTRIDE + p] = d[p] * exl;
    #pragma unroll
    for (int p = PDIM; p < 31; p++) eproba[(size_t)n * PSTRIDE + p] = 0.f;
    eproba[(size_t)n * PSTRIDE + 31] = exl;
}

// ---------------- K2: build W (bf16), warp per node, smem accumulation ----------------
__global__ void __launch_bounds__(256) k_build_W(
    const int* __restrict__ srcs, const int* __restrict__ off,
    const float* __restrict__ eproba,
    __nv_bfloat16* __restrict__ A, float* __restrict__ rden)
{
    __shared__ float sW[8][RDIM * 32];
    int w = (blockIdx.x * blockDim.x + threadIdx.x) >> 5;
    int wl = (threadIdx.x >> 5);
    int lane = threadIdx.x & 31;
    if (w >= NNODES) return;
    float* W = sW[wl];
    size_t rowoff = (size_t)w * KUF;
    int beg = __ldg(&off[w]);
    int end = __ldg(&off[w + 1]);

    // zero slab + pad columns 324..351
    #pragma unroll
    for (int r = 0; r < RDIM; r++) W[r * 32 + lane] = 0.f;
    if (lane < KUF - RDIM * PDIM)
        A[rowoff + RDIM * PDIM + lane] = __float2bfloat16(0.f);

    float den = 0.f;   // lane 31 sees sum of exl (eproba[..][31] = exl)
    int j = beg;
    for (; j + 1 < end; j += 2) {
        int p0 = __ldg(&srcs[j]);
        int p1 = __ldg(&srcs[j + 1]);
        float e0 = __ldg(&eproba[(size_t)(p0 & 0xFFFF) * PSTRIDE + lane]);
        float e1 = __ldg(&eproba[(size_t)(p1 & 0xFFFF) * PSTRIDE + lane]);
        den += e0 + e1;
        W[(p0 >> 16) * 32 + lane] += e0;
        W[(p1 >> 16) * 32 + lane] += e1;
    }
    if (j < end) {
        int p0 = __ldg(&srcs[j]);
        float e0 = __ldg(&eproba[(size_t)(p0 & 0xFFFF) * PSTRIDE + lane]);
        den += e0;
        W[(p0 >> 16) * 32 + lane] += e0;
    }

    // writeback: A[w][r*18+p] = bf16(W[r][p]) for p<18
    if (lane < PDIM) {
        #pragma unroll
        for (int r = 0; r < RDIM; r++)
            A[rowoff + r * PDIM + lane] = __float2bfloat16(W[r * 32 + lane]);
    }
    if (lane == 31) rden[w] = (beg == end) ? 0.f : (1.f / den);
}

// ---------------- K3: single-pass bf16 GEMM  C[NROWSx128] = A * B^T ----------------
__global__ void __launch_bounds__(256) k_gemm(
    const __nv_bfloat16* __restrict__ A_, const __nv_bfloat16* __restrict__ B_,
    const float* __restrict__ rden, float* __restrict__ out)
{
    extern __shared__ unsigned sm[];   // [2 stages][A 128*SMS + B 128*SMS] u32
    int tid = threadIdx.x;
    int wid = tid >> 5, lane = tid & 31;
    int wm = wid & 3, wn = wid >> 2;   // warp tile: 32 rows x 64 cols
    int g = lane >> 2, t = lane & 3;
    int rowbase = blockIdx.x * 128;

    const unsigned* Ag = (const unsigned*)A_;
    const unsigned* Bg = (const unsigned*)B_;

    float acc[2][8][4];
    #pragma unroll
    for (int mt = 0; mt < 2; mt++)
        #pragma unroll
        for (int nt = 0; nt < 8; nt++)
            #pragma unroll
            for (int c = 0; c < 4; c++) acc[mt][nt][c] = 0.f;

    const int STAGE = 2 * 128 * SMS;   // u32 per stage

    auto load_stage = [&](int stage, int kc) {
        unsigned* sb = sm + stage * STAGE;
        int kb = kc * 16;              // u32 col offset (32 bf16)
        #pragma unroll
        for (int i = 0; i < 2; i++) {
            int q = i * 256 + tid;
            int row = q >> 2;
            int c4 = (q & 3) * 4;
            cp_async16(sb + row * SMS + c4,
                       Ag + (size_t)(rowbase + row) * KU32 + kb + c4);
            cp_async16(sb + 128 * SMS + row * SMS + c4,
                       Bg + (size_t)row * KU32 + kb + c4);
        }
        CP_COMMIT();
    };

    load_stage(0, 0);

    #pragma unroll 1
    for (int kc = 0; kc < NCH; kc++) {
        int cur = kc & 1;
        if (kc + 1 < NCH) { load_stage(cur ^ 1, kc + 1); CP_WAIT(1); }
        else              { CP_WAIT(0); }
        __syncthreads();

        unsigned* As = sm + cur * STAGE;
        unsigned* Bs = As + 128 * SMS;

        #pragma unroll
        for (int ks = 0; ks < 2; ks++) {   // two k16 steps per 32-col chunk
            int kb8 = ks * 8;
            unsigned a[2][4];
            #pragma unroll
            for (int mt = 0; mt < 2; mt++) {
                int mr = wm * 32 + mt * 16 + g;
                a[mt][0] = As[mr * SMS + kb8 + t];
                a[mt][1] = As[(mr + 8) * SMS + kb8 + t];
                a[mt][2] = As[mr * SMS + kb8 + t + 4];
                a[mt][3] = As[(mr + 8) * SMS + kb8 + t + 4];
            }
            #pragma unroll
            for (int nt = 0; nt < 8; nt++) {
                int nr = wn * 64 + nt * 8 + g;
                unsigned b[2];
                b[0] = Bs[nr * SMS + kb8 + t];
                b[1] = Bs[nr * SMS + kb8 + t + 4];
                #pragma unroll
                for (int mt = 0; mt < 2; mt++) mma_bf16(acc[mt][nt], a[mt], b);
            }
        }
        __syncthreads();
    }

    // epilogue: scale by 1/den, guarded store
    #pragma unroll
    for (int mt = 0; mt < 2; mt++) {
        int r0 = rowbase + wm * 32 + mt * 16 + g;
        int r1 = r0 + 8;
        float s0v = (r0 < NNODES) ? __ldg(&rden[r0]) : 0.f;
        float s1v = (r1 < NNODES) ? __ldg(&rden[r1]) : 0.f;
        #pragma unroll
        for (int nt = 0; nt < 8; nt++) {
            int col = wn * 64 + nt * 8 + t * 2;
            if (r0 < NNODES) {
                float2 v = make_float2(acc[mt][nt][0] * s0v, acc[mt][nt][1] * s0v);
                *(float2*)(out + (size_t)r0 * HDIM + col) = v;
            }
            if (r1 < NNODES) {
                float2 v = make_float2(acc[mt][nt][2] * s1v, acc[mt][nt][3] * s1v);
                *(float2*)(out + (size_t)r1 * HDIM + col) = v;
            }
        }
    }
}

// ---------------- classifier ----------------
__global__ void __launch_bounds__(128) k_classifier(
    const float* __restrict__ hidden, const int* __restrict__ tails,
    const float* __restrict__ proto, float* __restrict__ out, int B)
{
    __shared__ float ps[PDIM * HDIM];
    proto_to_smem(proto, ps);
    int t = blockIdx.x * blockDim.x + threadIdx.x;
    if (t >= B) return;
    const float4* hp = (const float4*)(hidden + (size_t)__ldg(&tails[t]) * HDIM);
    float d[PDIM];
    #pragma unroll
    for (int p = 0; p < PDIM; p++) d[p] = 0.f;
    float ss = 0.f;
    for (int i = 0; i < HDIM / 4; i++) {
        float4 h = __ldg(hp + i);
        ss += h.x * h.x + h.y * h.y + h.z * h.z + h.w * h.w;
        #pragma unroll
        for (int p = 0; p < PDIM; p++) {
            float4 q = *(const float4*)(ps + p * HDIM + i * 4);
            d[p] += h.x * q.x + h.y * q.y + h.z * q.z + h.w * q.w;
        }
    }
    float inv = 1.f / fmaxf(sqrtf(ss), 1e-12f);
    #pragma unroll
    for (int p = 0; p < PDIM; p++) out[(size_t)t * PDIM + p] = d[p] * inv;
}

// ---------------- host ----------------
static inline int grd(int n, int b) { return (n + b - 1) / b; }

extern "C" void kernel_launch(void* const* d_in, const int* in_sizes, int n_in,
                              void* d_out, int out_size)
{
    const int*   edge_index = (const int*)d_in[0];
    const int*   etype      = (const int*)d_in[1];
    const int*   tails      = (const int*)d_in[2];
    const float* multi      = (const float*)d_in[3];
    const float* proto      = (const float*)d_in[4];
    const float* semb       = (const float*)d_in[5];
    float* out = (float*)d_out;

    int E = in_sizes[0] / 2;
    int B = in_sizes[2];
    int L = in_sizes[3] / (RDIM * PDIM * HDIM);
    const int* src = edge_index;
    const int* dst = edge_index + E;

    float *hid0, *hid1, *eproba, *rden;
    __nv_bfloat16 *A, *Bm;
    int *cnt, *off, *bsum, *srcs;
    cudaGetSymbolAddress((void**)&hid0,   g_hidden0);
    cudaGetSymbolAddress((void**)&hid1,   g_hidden1);
    cudaGetSymbolAddress((void**)&eproba, g_eproba);
    cudaGetSymbolAddress((void**)&rden,   g_rden);
    cudaGetSymbolAddress((void**)&A,      g_A);
    cudaGetSymbolAddress((void**)&Bm,     g_B);
    cudaGetSymbolAddress((void**)&cnt,    g_cnt);
    cudaGetSymbolAddress((void**)&off,    g_off);
    cudaGetSymbolAddress((void**)&bsum,   g_bsum);
    cudaGetSymbolAddress((void**)&srcs,   g_srcs);

    const int TB = 256;
    const int GEMM_SMEM = 2 * 2 * 128 * SMS * 4;   // 40960 B
    cudaFuncSetAttribute(k_gemm, cudaFuncAttributeMaxDynamicSharedMemorySize, GEMM_SMEM);

    // ---- preprocessing: counting sort of edges by dst + B build ----
    k_setup<<<grd(NNODES * HDIM, TB), TB>>>(cnt, hid0, semb, A, multi, Bm, L * 128 * KUF);
    k_hist<<<grd(E, TB), TB>>>(dst, cnt, E);
    int nb = grd(NNODES, SCAN_B);
    k_scan1<<<nb, SCAN_B>>>(cnt, off, bsum, NNODES);
    k_scan2<<<1, SCAN_B>>>(bsum, nb);
    k_scan3<<<grd(NNODES + 1, TB), TB>>>(off, bsum, cnt, NNODES, E);
    k_rank<<<grd(E, TB), TB>>>(dst, etype, src, off, cnt, srcs, E);

    float* cur = hid0;
    float* nxt = hid1;
    for (int l = 0; l < L; l++) {
        k_node_logits<<<grd(NNODES, 128), 128>>>(
            cur, proto + (size_t)l * PDIM * HDIM, eproba, NNODES);
        k_build_W<<<grd(NNODES * 32, TB), TB>>>(srcs, off, eproba, A, rden);
        k_gemm<<<NTILES, 256, GEMM_SMEM>>>(A, Bm + (size_t)l * 128 * KUF, rden, nxt);
        float* tmp = cur; cur = nxt; nxt = tmp;
    }

    k_classifier<<<grd(B, 128), 128>>>(
        cur, tails, proto + (size_t)(L - 1) * PDIM * HDIM, out, B);
}

// round 8
// speedup vs baseline: 5.5872x; 1.1192x over previous
#include <cuda_runtime.h>
#include <cuda_bf16.h>
#include <cstdint>

#define HDIM 128
#define PDIM 18
#define RDIM 18
#define NNODES 50000
#define NTILES 391
#define NROWS (NTILES * 128)     // 50048
#define MAXE 800000
#define PSTRIDE 32               // eproba row stride (bf16)
#define KUF 352                  // K padded (bf16 elems per row)
#define KU32 176                 // u32 (bf16x2) per row
#define NCH 11                   // k chunks of 32 bf16 (16 u32)
#define SMS 20                   // pipeline smem row stride in u32
#define CTS 129                  // epilogue C-tile stride (f32)
#define PS_OFF 16512             // f32 offset of protos in gemm smem (128*129)
#define LMAX 3

// ---------------- scratch (device globals; no allocations allowed) ----------------
__device__ float         g_hidden[NNODES * HDIM];     // last-layer output only
__device__ __nv_bfloat16 g_eproba[NNODES * PSTRIDE];  // [n][p]=exl*proba, [n][31]=exl
__device__ float         g_rden[NNODES];
__device__ __nv_bfloat16 g_A[(size_t)NROWS * KUF];
__device__ __nv_bfloat16 g_B[LMAX * 128 * KUF];
__device__ int           g_cnt[NNODES];
__device__ int           g_off[NNODES + 1];
__device__ int           g_srcs[MAXE];                // packed src | (r<<16), sorted by dst

// ---------------- helpers ----------------
__device__ __forceinline__ void cp_async16(void* sdst, const void* gsrc) {
    unsigned s = (unsigned)__cvta_generic_to_shared(sdst);
    asm volatile("cp.async.cg.shared.global [%0], [%1], 16;\n" :: "r"(s), "l"(gsrc));
}
#define CP_COMMIT() asm volatile("cp.async.commit_group;\n" ::: "memory")
#define CP_WAIT(n)  asm volatile("cp.async.wait_group %0;\n" :: "n"(n) : "memory")

__device__ __forceinline__ void mma_bf16(float* c, const unsigned* a, const unsigned* b) {
    asm volatile(
        "mma.sync.aligned.m16n8k16.row.col.f32.bf16.bf16.f32 "
        "{%0,%1,%2,%3}, {%4,%5,%6,%7}, {%8,%9}, {%0,%1,%2,%3};\n"
        : "+f"(c[0]), "+f"(c[1]), "+f"(c[2]), "+f"(c[3])
        : "r"(a[0]), "r"(a[1]), "r"(a[2]), "r"(a[3]), "r"(b[0]), "r"(b[1]));
}

__device__ __forceinline__ uint32_t pack_bf2(float lo, float hi) {
    __nv_bfloat162 t = __floats2bfloat162_rn(lo, hi);
    return *(uint32_t*)&t;
}

// normalize PDIM proto rows into smem ps[] (whole block; any blockDim multiple of 32)
__device__ __forceinline__ void proto_to_smem(const float* __restrict__ proto, float* ps) {
    int warp = threadIdx.x >> 5, lane = threadIdx.x & 31;
    int nw = blockDim.x >> 5;
    for (int p = warp; p < PDIM; p += nw) {
        float4 v = ((const float4*)(proto + p * HDIM))[lane];
        float ss = v.x * v.x + v.y * v.y + v.z * v.z + v.w * v.w;
        #pragma unroll
        for (int o = 16; o; o >>= 1) ss += __shfl_xor_sync(0xffffffffu, ss, o);
        float inv = 1.f / fmaxf(sqrtf(ss), 1e-12f);
        ((float4*)(ps + p * HDIM))[lane] = make_float4(v.x * inv, v.y * inv, v.z * inv, v.w * inv);
    }
    __syncthreads();
}

// ---------------- setup: zero cnt + A pad rows + build B + uniform layer-0 eproba ----------------
__global__ void k_setup(int* __restrict__ cnt,
                        __nv_bfloat16* __restrict__ A,
                        const float* __restrict__ M, __nv_bfloat16* __restrict__ B,
                        __nv_bfloat16* __restrict__ eproba, int btotal) {
    int i = blockIdx.x * blockDim.x + threadIdx.x;
    if (i < NNODES) cnt[i] = 0;
    if (i < (NROWS - NNODES) * KUF)
        A[(size_t)NNODES * KUF + i] = __float2bfloat16(0.f);
    if (i < btotal) {                   // B[l][h][k] = bf16(M[l][k/18][k%18][h])
        int l = i / (128 * KUF);
        int rem = i - l * 128 * KUF;
        int h = rem / KUF, k = rem % KUF;
        float v = 0.f;
        if (k < RDIM * PDIM)
            v = __ldg(&M[(size_t)((l * RDIM + k / PDIM) * PDIM + k % PDIM) * HDIM + h]);
        B[i] = __float2bfloat16(v);
    }
    if (i < NNODES * PSTRIDE) {
        // zero hidden -> uniform proba 1/18, exl = exp(log(1/18+1e-8)) = 1/18+1e-8
        const float pu = 1.f / 18.f;
        const float exlu = pu + 1e-8f;
        int k = i & 31;
        float v = (k < PDIM) ? pu * exlu : ((k == 31) ? exlu : 0.f);
        eproba[i] = __float2bfloat16(v);
    }
}

// ---------------- hist ----------------
__global__ void k_hist(const int* __restrict__ dst, int* __restrict__ cnt, int E) {
    int e = blockIdx.x * blockDim.x + threadIdx.x;
    if (e < E) atomicAdd(&cnt[dst[e]], 1);
}

// ---------------- single-block scan over 50K counters + node-0 eproba fix ----------------
__global__ void __launch_bounds__(1024) k_scanall(
    int* __restrict__ cnt, int* __restrict__ off,
    const float* __restrict__ proto0, const float* __restrict__ semb,
    __nv_bfloat16* __restrict__ eproba, int E)
{
    __shared__ int wsum[32];
    int tid = threadIdx.x, lane = tid & 31, wid = tid >> 5;
    int carry = 0;
    const int ROUNDS = (NNODES + 1023) / 1024;
    for (int rd = 0; rd < ROUNDS; rd++) {
        int i = rd * 1024 + tid;
        int v = (i < NNODES) ? cnt[i] : 0;
        int x = v;
        #pragma unroll
        for (int o = 1; o < 32; o <<= 1) {
            int y = __shfl_up_sync(0xffffffffu, x, o);
            if (lane >= o) x += y;
        }
        if (lane == 31) wsum[wid] = x;
        __syncthreads();
        if (wid == 0) {
            int wv = wsum[lane];
            #pragma unroll
            for (int o = 1; o < 32; o <<= 1) {
                int y = __shfl_up_sync(0xffffffffu, wv, o);
                if (lane >= o) wv += y;
            }
            wsum[lane] = wv;
        }
        __syncthreads();
        int base = (wid > 0) ? wsum[wid - 1] : 0;
        if (i < NNODES) { off[i] = carry + base + x - v; cnt[i] = 0; }
        carry += wsum[31];
        __syncthreads();
    }
    if (tid == 0) off[NNODES] = E;

    // node 0: real eproba row from semb vs layer-0 protos (one warp)
    if (wid == 0) {
        float4 h = ((const float4*)semb)[lane];
        float ss = h.x * h.x + h.y * h.y + h.z * h.z + h.w * h.w;
        #pragma unroll
        for (int o = 16; o; o >>= 1) ss += __shfl_xor_sync(0xffffffffu, ss, o);
        float inv = 1.f / fmaxf(sqrtf(ss), 1e-12f);
        float d[PDIM];
        #pragma unroll
        for (int p = 0; p < PDIM; p++) {
            float4 q = ((const float4*)(proto0 + p * HDIM))[lane];
            float sp = q.x * q.x + q.y * q.y + q.z * q.z + q.w * q.w;
            float dp = h.x * q.x + h.y * q.y + h.z * q.z + h.w * q.w;
            #pragma unroll
            for (int o = 16; o; o >>= 1) {
                sp += __shfl_xor_sync(0xffffffffu, sp, o);
                dp += __shfl_xor_sync(0xffffffffu, dp, o);
            }
            d[p] = dp * inv / fmaxf(sqrtf(sp), 1e-12f);
        }
        float mx = -1e30f;
        #pragma unroll
        for (int p = 0; p < PDIM; p++) mx = fmaxf(mx, d[p]);
        float sum = 0.f;
        #pragma unroll
        for (int p = 0; p < PDIM; p++) { d[p] = expf(d[p] - mx); sum += d[p]; }
        float rs = 1.f / sum;
        float ent = 0.f;
        #pragma unroll
        for (int p = 0; p < PDIM; p++) { d[p] *= rs; ent -= d[p] * logf(d[p] + 1e-8f); }
        float exl = expf(-ent);
        if (lane == 0) {
            uint32_t* row = (uint32_t*)eproba;   // node 0
            #pragma unroll
            for (int j = 0; j < 16; j++) {
                float lo = (2 * j < PDIM) ? d[2 * j] * exl : 0.f;
                float hi = (2 * j + 1 < PDIM) ? d[2 * j + 1] * exl
                                              : ((2 * j + 1 == 31) ? exl : 0.f);
                row[j] = pack_bf2(lo, hi);
            }
        }
    }
}

// ---------------- rank ----------------
__global__ void k_rank(const int* __restrict__ dst, const int* __restrict__ et,
                       const int* __restrict__ src,
                       const int* __restrict__ off, int* __restrict__ run,
                       int* __restrict__ srcs, int E) {
    int e = blockIdx.x * blockDim.x + threadIdx.x;
    if (e >= E) return;
    int d = dst[e];
    int pos = off[d] + atomicAdd(&run[d], 1);
    srcs[pos] = src[e] | (et[e] << 16);
}

// ---------------- build W (bf16 eproba in, bf16 A out), warp per node ----------------
__global__ void __launch_bounds__(256) k_build_W(
    const int* __restrict__ srcs, const int* __restrict__ off,
    const __nv_bfloat16* __restrict__ eproba,
    __nv_bfloat16* __restrict__ A, float* __restrict__ rden)
{
    __shared__ float sW[8][RDIM * 32];
    int w = (blockIdx.x * blockDim.x + threadIdx.x) >> 5;
    int wl = (threadIdx.x >> 5);
    int lane = threadIdx.x & 31;
    if (w >= NNODES) return;
    float* W = sW[wl];
    size_t rowoff = (size_t)w * KUF;
    int beg = __ldg(&off[w]);
    int end = __ldg(&off[w + 1]);

    #pragma unroll
    for (int r = 0; r < RDIM; r++) W[r * 32 + lane] = 0.f;
    if (lane < KUF - RDIM * PDIM)
        A[rowoff + RDIM * PDIM + lane] = __float2bfloat16(0.f);

    float den = 0.f;   // lane 31 accumulates exl
    int j = beg;
    for (; j + 1 < end; j += 2) {
        int p0 = __ldg(&srcs[j]);
        int p1 = __ldg(&srcs[j + 1]);
        float e0 = __bfloat162float(__ldg(&eproba[(size_t)(p0 & 0xFFFF) * PSTRIDE + lane]));
        float e1 = __bfloat162float(__ldg(&eproba[(size_t)(p1 & 0xFFFF) * PSTRIDE + lane]));
        den += e0 + e1;
        W[(p0 >> 16) * 32 + lane] += e0;
        W[(p1 >> 16) * 32 + lane] += e1;
    }
    if (j < end) {
        int p0 = __ldg(&srcs[j]);
        float e0 = __bfloat162float(__ldg(&eproba[(size_t)(p0 & 0xFFFF) * PSTRIDE + lane]));
        den += e0;
        W[(p0 >> 16) * 32 + lane] += e0;
    }

    if (lane < PDIM) {
        #pragma unroll
        for (int r = 0; r < RDIM; r++)
            A[rowoff + r * PDIM + lane] = __float2bfloat16(W[r * 32 + lane]);
    }
    if (lane == 31) rden[w] = (beg == end) ? 0.f : (1.f / den);
}

// ---------------- GEMM + fused next-layer logits epilogue ----------------
// If ep_out != null: stage C in smem, compute eproba for next layer (proto_next).
// Else: store scaled C rows to hid_out (last layer).
__global__ void __launch_bounds__(256) k_gemm(
    const __nv_bfloat16* __restrict__ A_, const __nv_bfloat16* __restrict__ B_,
    const float* __restrict__ rden,
    const float* __restrict__ proto_next,
    __nv_bfloat16* __restrict__ ep_out,
    float* __restrict__ hid_out)
{
    extern __shared__ unsigned sm[];
    int tid = threadIdx.x;
    int wid = tid >> 5, lane = tid & 31;
    int wm = wid & 3, wn = wid >> 2;
    int g = lane >> 2, t = lane & 3;
    int rowbase = blockIdx.x * 128;

    if (ep_out) proto_to_smem(proto_next, (float*)sm + PS_OFF);

    const unsigned* Ag = (const unsigned*)A_;
    const unsigned* Bg = (const unsigned*)B_;

    float acc[2][8][4];
    #pragma unroll
    for (int mt = 0; mt < 2; mt++)
        #pragma unroll
        for (int nt = 0; nt < 8; nt++)
            #pragma unroll
            for (int c = 0; c < 4; c++) acc[mt][nt][c] = 0.f;

    const int STAGE = 2 * 128 * SMS;

    auto load_stage = [&](int stage, int kc) {
        unsigned* sb = sm + stage * STAGE;
        int kb = kc * 16;
        #pragma unroll
        for (int i = 0; i < 2; i++) {
            int q = i * 256 + tid;
            int row = q >> 2;
            int c4 = (q & 3) * 4;
            cp_async16(sb + row * SMS + c4, Ag + (size_t)(rowbase + row) * KU32 + kb + c4);
            cp_async16(sb + 128 * SMS + row * SMS + c4, Bg + (size_t)row * KU32 + kb + c4);
        }
        CP_COMMIT();
    };

    load_stage(0, 0);

    #pragma unroll 1
    for (int kc = 0; kc < NCH; kc++) {
        int cur = kc & 1;
        if (kc + 1 < NCH) { load_stage(cur ^ 1, kc + 1); CP_WAIT(1); }
        else              { CP_WAIT(0); }
        __syncthreads();

        unsigned* As = sm + cur * STAGE;
        unsigned* Bs = As + 128 * SMS;

        #pragma unroll
        for (int ks = 0; ks < 2; ks++) {
            int kb8 = ks * 8;
            unsigned a[2][4];
            #pragma unroll
            for (int mt = 0; mt < 2; mt++) {
                int mr = wm * 32 + mt * 16 + g;
                a[mt][0] = As[mr * SMS + kb8 + t];
                a[mt][1] = As[(mr + 8) * SMS + kb8 + t];
                a[mt][2] = As[mr * SMS + kb8 + t + 4];
                a[mt][3] = As[(mr + 8) * SMS + kb8 + t + 4];
            }
            #pragma unroll
            for (int nt = 0; nt < 8; nt++) {
                int nr = wn * 64 + nt * 8 + g;
                unsigned b[2];
                b[0] = Bs[nr * SMS + kb8 + t];
                b[1] = Bs[nr * SMS + kb8 + t + 4];
                #pragma unroll
                for (int mt = 0; mt < 2; mt++) mma_bf16(acc[mt][nt], a[mt], b);
            }
        }
        __syncthreads();
    }

    if (ep_out == nullptr) {
        // last layer: direct store to hidden
        #pragma unroll
        for (int mt = 0; mt < 2; mt++) {
            int r0 = rowbase + wm * 32 + mt * 16 + g;
            int r1 = r0 + 8;
            float s0v = (r0 < NNODES) ? __ldg(&rden[r0]) : 0.f;
            float s1v = (r1 < NNODES) ? __ldg(&rden[r1]) : 0.f;
            #pragma unroll
            for (int nt = 0; nt < 8; nt++) {
                int col = wn * 64 + nt * 8 + t * 2;
                if (r0 < NNODES)
                    *(float2*)(hid_out + (size_t)r0 * HDIM + col) =
                        make_float2(acc[mt][nt][0] * s0v, acc[mt][nt][1] * s0v);
                if (r1 < NNODES)
                    *(float2*)(hid_out + (size_t)r1 * HDIM + col) =
                        make_float2(acc[mt][nt][2] * s1v, acc[mt][nt][3] * s1v);
            }
        }
        return;
    }

    // fused logits: stage scaled C tile into smem (pipeline area is dead)
    float* ct = (float*)sm;
    #pragma unroll
    for (int mt = 0; mt < 2; mt++) {
        int r0l = wm * 32 + mt * 16 + g;
        int r1l = r0l + 8;
        int gr0 = rowbase + r0l, gr1 = rowbase + r1l;
        float s0v = (gr0 < NNODES) ? __ldg(&rden[gr0]) : 0.f;
        float s1v = (gr1 < NNODES) ? __ldg(&rden[gr1]) : 0.f;
        #pragma unroll
        for (int nt = 0; nt < 8; nt++) {
            int col = wn * 64 + nt * 8 + t * 2;
            ct[r0l * CTS + col]     = acc[mt][nt][0] * s0v;
            ct[r0l * CTS + col + 1] = acc[mt][nt][1] * s0v;
            ct[r1l * CTS + col]     = acc[mt][nt][2] * s1v;
            ct[r1l * CTS + col + 1] = acc[mt][nt][3] * s1v;
        }
    }
    __syncthreads();

    if (tid < 128) {
        int row = tid;
        int gr = rowbase + row;
        if (gr < NNODES) {
            const float* hr  = ct + row * CTS;
            const float* psn = (const float*)sm + PS_OFF;
            float ss = 0.f;
            float d[PDIM];
            #pragma unroll
            for (int p = 0; p < PDIM; p++) d[p] = 0.f;
            #pragma unroll 4
            for (int i = 0; i < HDIM; i++) {
                float hv = hr[i];
                ss += hv * hv;
                #pragma unroll
                for (int p = 0; p < PDIM; p++) d[p] += hv * psn[p * HDIM + i];
            }
            float inv = 1.f / fmaxf(sqrtf(ss), 1e-12f);
            float mx = -1e30f;
            #pragma unroll
            for (int p = 0; p < PDIM; p++) { d[p] *= inv; mx = fmaxf(mx, d[p]); }
            float sum = 0.f;
            #pragma unroll
            for (int p = 0; p < PDIM; p++) { d[p] = expf(d[p] - mx); sum += d[p]; }
            float rs = 1.f / sum;
            float ent = 0.f;
            #pragma unroll
            for (int p = 0; p < PDIM; p++) { d[p] *= rs; ent -= d[p] * logf(d[p] + 1e-8f); }
            float exl = expf(-ent);
            uint32_t w32[16];
            #pragma unroll
            for (int j = 0; j < 16; j++) {
                float lo = (2 * j < PDIM) ? d[2 * j] * exl : 0.f;
                float hi = (2 * j + 1 < PDIM) ? d[2 * j + 1] * exl
                                              : ((2 * j + 1 == 31) ? exl : 0.f);
                w32[j] = pack_bf2(lo, hi);
            }
            uint4* dp4 = (uint4*)((uint32_t*)ep_out + (size_t)gr * 16);
            dp4[0] = make_uint4(w32[0], w32[1], w32[2], w32[3]);
            dp4[1] = make_uint4(w32[4], w32[5], w32[6], w32[7]);
            dp4[2] = make_uint4(w32[8], w32[9], w32[10], w32[11]);
            dp4[3] = make_uint4(w32[12], w32[13], w32[14], w32[15]);
        }
    }
}

// ---------------- classifier ----------------
__global__ void __launch_bounds__(128) k_classifier(
    const float* __restrict__ hidden, const int* __restrict__ tails,
    const float* __restrict__ proto, float* __restrict__ out, int B)
{
    __shared__ float ps[PDIM * HDIM];
    proto_to_smem(proto, ps);
    int t = blockIdx.x * blockDim.x + threadIdx.x;
    if (t >= B) return;
    const float4* hp = (const float4*)(hidden + (size_t)__ldg(&tails[t]) * HDIM);
    float d[PDIM];
    #pragma unroll
    for (int p = 0; p < PDIM; p++) d[p] = 0.f;
    float ss = 0.f;
    for (int i = 0; i < HDIM / 4; i++) {
        float4 h = __ldg(hp + i);
        ss += h.x * h.x + h.y * h.y + h.z * h.z + h.w * h.w;
        #pragma unroll
        for (int p = 0; p < PDIM; p++) {
            float4 q = *(const float4*)(ps + p * HDIM + i * 4);
            d[p] += h.x * q.x + h.y * q.y + h.z * q.z + h.w * q.w;
        }
    }
    float inv = 1.f / fmaxf(sqrtf(ss), 1e-12f);
    #pragma unroll
    for (int p = 0; p < PDIM; p++) out[(size_t)t * PDIM + p] = d[p] * inv;
}

// ---------------- host ----------------
static inline int grd(int n, int b) { return (n + b - 1) / b; }

extern "C" void kernel_launch(void* const* d_in, const int* in_sizes, int n_in,
                              void* d_out, int out_size)
{
    const int*   edge_index = (const int*)d_in[0];
    const int*   etype      = (const int*)d_in[1];
    const int*   tails      = (const int*)d_in[2];
    const float* multi      = (const float*)d_in[3];
    const float* proto      = (const float*)d_in[4];
    const float* semb       = (const float*)d_in[5];
    float* out = (float*)d_out;

    int E = in_sizes[0] / 2;
    int B = in_sizes[2];
    int L = in_sizes[3] / (RDIM * PDIM * HDIM);
    const int* src = edge_index;
    const int* dst = edge_index + E;

    float *hid, *rden;
    __nv_bfloat16 *eproba, *A, *Bm;
    int *cnt, *off, *srcs;
    cudaGetSymbolAddress((void**)&hid,    g_hidden);
    cudaGetSymbolAddress((void**)&eproba, g_eproba);
    cudaGetSymbolAddress((void**)&rden,   g_rden);
    cudaGetSymbolAddress((void**)&A,      g_A);
    cudaGetSymbolAddress((void**)&Bm,     g_B);
    cudaGetSymbolAddress((void**)&cnt,    g_cnt);
    cudaGetSymbolAddress((void**)&off,    g_off);
    cudaGetSymbolAddress((void**)&srcs,   g_srcs);

    const int TB = 256;
    const int SM_PLAIN = 2 * 2 * 128 * SMS * 4;             // 40960
    const int SM_FUSED = (PS_OFF + PDIM * HDIM) * 4;        // 75264
    cudaFuncSetAttribute(k_gemm, cudaFuncAttributeMaxDynamicSharedMemorySize, SM_FUSED);

    // ---- preprocessing ----
    k_setup<<<grd(NNODES * PSTRIDE, TB), TB>>>(cnt, A, multi, Bm, eproba, L * 128 * KUF);
    k_hist<<<grd(E, TB), TB>>>(dst, cnt, E);
    k_scanall<<<1, 1024>>>(cnt, off, proto, semb, eproba, E);
    k_rank<<<grd(E, TB), TB>>>(dst, etype, src, off, cnt, srcs, E);

    for (int l = 0; l < L; l++) {
        bool last = (l == L - 1);
        k_build_W<<<grd(NNODES * 32, TB), TB>>>(srcs, off, eproba, A, rden);
        k_gemm<<<NTILES, 256, last ? SM_PLAIN : SM_FUSED>>>(
            A, Bm + (size_t)l * 128 * KUF, rden,
            last ? nullptr : proto + (size_t)(l + 1) * PDIM * HDIM,
            last ? nullptr : eproba,
            last ? hid : nullptr);
    }

    k_classifier<<<grd(B, 128), 128>>>(
        hid, tails, proto + (size_t)(L - 1) * PDIM * HDIM, out, B);
}